// round 2
// baseline (speedup 1.0000x reference)
#include <cuda_runtime.h>
#include <cuda_bf16.h>
#include <math.h>

#define BB 4
#define TT 1024
#define CC 2048
#define HH 16
#define DD 128

typedef unsigned long long u64;

__device__ __forceinline__ u64 fma2(u64 a, u64 b, u64 c) {
    u64 d;
    asm("fma.rn.f32x2 %0, %1, %2, %3;" : "=l"(d) : "l"(a), "l"(b), "l"(c));
    return d;
}
__device__ __forceinline__ u64 mul2(u64 a, u64 b) {
    u64 d;
    asm("mul.rn.f32x2 %0, %1, %2;" : "=l"(d) : "l"(a), "l"(b));
    return d;
}
__device__ __forceinline__ u64 pack2(float x, float y) {
    u64 d;
    asm("mov.b64 %0, {%1, %2};" : "=l"(d) : "f"(x), "f"(y));
    return d;
}
__device__ __forceinline__ float2 unpack2(u64 v) {
    float2 r;
    asm("mov.b64 {%0, %1}, %2;" : "=f"(r.x), "=f"(r.y) : "l"(v));
    return r;
}

// Scratch (no allocation allowed -> device globals)
__device__ float g_q[8388608];   // (B,H,T,D)
__device__ float g_k[8388608];
__device__ float g_v[8388608];
__device__ float g_y[8388608];   // (B,T,C) attention output
__device__ float g_u[196608];    // (B,T,48)  x @ [dqA;dkA;dvA]^T
__device__ float g_uo[65536];    // (B,T,16)  y @ doA^T

// ---------------------------------------------------------------------------
// Low-rank left factor. mode 0: U = x @ dA^T (48 cols; dA rows 0-15,32-47,64-79)
//                       mode 1: Uo = y @ doA^T (16 cols; rows 96-111)
// ---------------------------------------------------------------------------
__global__ void lora_u_kernel(const float* __restrict__ x,
                              const float* __restrict__ delta, int mode)
{
    int bt = blockIdx.x;
    int b  = bt >> 10;
    const float* src  = (mode == 0) ? x : (const float*)g_y;
    const float* xrow = src + (size_t)bt * CC;
    float* dst = (mode == 0) ? g_u : g_uo;
    int nOut   = (mode == 0) ? 48 : 16;

    int lane = threadIdx.x & 31, w = threadIdx.x >> 5;
    for (int j = w; j < nOut; j += 8) {
        int row = (mode == 0) ? ((j >> 4) * 32 + (j & 15)) : (96 + j);
        const float* arow = delta + ((size_t)b * 128 + row) * CC;
        float s = 0.f;
        for (int i = lane * 4; i < CC; i += 128) {
            float4 xv = *(const float4*)(xrow + i);
            float4 av = *(const float4*)(arow + i);
            s += xv.x * av.x + xv.y * av.y + xv.z * av.z + xv.w * av.w;
        }
        #pragma unroll
        for (int o = 16; o; o >>= 1) s += __shfl_xor_sync(0xffffffffu, s, o);
        if (lane == 0) dst[(size_t)bt * nOut + j] = s;
    }
}

// ---------------------------------------------------------------------------
// Projection GEMM: out[m,n] = sum_k A[m,k]*W[n,k] + LoRA low-rank term.
// 64(M) x 128(N) tile, Kt=16, 256 threads, 4m x 8n micro in f32x2.
// mode 0: fused QKV (N=6144 over Wq|Wk|Wv), writes (B,H,T,D) head layout.
// mode 1: Wo on g_y, writes d_out (B,T,C).
// ---------------------------------------------------------------------------
__global__ __launch_bounds__(256, 2) void proj_kernel(
    const float* __restrict__ X,
    const float* __restrict__ Wq, const float* __restrict__ Wk,
    const float* __restrict__ Wv, const float* __restrict__ Wo,
    const float* __restrict__ delta, int mode, float* __restrict__ outO)
{
    __shared__ __align__(16) u64   sA2[2 * 16 * 66];   // [buf][k][m] (a,a)
    __shared__ __align__(16) float sB [2 * 16 * 132];  // [buf][k][n]

    const int b = blockIdx.z, mt = blockIdx.y, nt = blockIdx.x;
    const int m0 = mt * 64, nbase = nt * 128;

    const float* W; const float* U; const float* Xin;
    int ncol0, dbrow, uoff, ustride;
    if (mode == 0) {
        int seg = nbase >> 11;
        ncol0 = nbase & 2047;
        W = (seg == 0) ? Wq : (seg == 1 ? Wk : Wv);
        dbrow = seg * 32 + 16; uoff = seg * 16;
        U = g_u; ustride = 48; Xin = X;
    } else {
        W = Wo; ncol0 = nbase; dbrow = 112; uoff = 0;
        U = g_uo; ustride = 16; Xin = (const float*)g_y;
    }
    const float* Xb = Xin + (size_t)b * TT * CC;

    const int tid = threadIdx.x;
    const int tx = tid & 15, ty = tid >> 4;
    const int arow = tid >> 2, ac4 = (tid & 3) * 4;
    const float* Ap  = Xb + (size_t)(m0 + arow) * CC + ac4;
    const float* Bp0 = W  + (size_t)(ncol0 + arow) * CC + ac4;
    const float* Bp1 = Bp0 + (size_t)64 * CC;

    float4 apf  = *(const float4*)Ap;
    float4 bpf0 = *(const float4*)Bp0;
    float4 bpf1 = *(const float4*)Bp1;
    {
        u64* sa = sA2; float* sb = sB;
        sa[(ac4 + 0) * 66 + arow] = pack2(apf.x, apf.x);
        sa[(ac4 + 1) * 66 + arow] = pack2(apf.y, apf.y);
        sa[(ac4 + 2) * 66 + arow] = pack2(apf.z, apf.z);
        sa[(ac4 + 3) * 66 + arow] = pack2(apf.w, apf.w);
        sb[(ac4 + 0) * 132 + arow] = bpf0.x;
        sb[(ac4 + 1) * 132 + arow] = bpf0.y;
        sb[(ac4 + 2) * 132 + arow] = bpf0.z;
        sb[(ac4 + 3) * 132 + arow] = bpf0.w;
        sb[(ac4 + 0) * 132 + arow + 64] = bpf1.x;
        sb[(ac4 + 1) * 132 + arow + 64] = bpf1.y;
        sb[(ac4 + 2) * 132 + arow + 64] = bpf1.z;
        sb[(ac4 + 3) * 132 + arow + 64] = bpf1.w;
    }
    __syncthreads();

    u64 acc[4][4];
    #pragma unroll
    for (int i = 0; i < 4; i++)
        #pragma unroll
        for (int j = 0; j < 4; j++) acc[i][j] = 0ULL;

    for (int kt = 0; kt < 128; kt++) {
        if (kt < 127) {
            apf  = *(const float4*)(Ap  + (kt + 1) * 16);
            bpf0 = *(const float4*)(Bp0 + (kt + 1) * 16);
            bpf1 = *(const float4*)(Bp1 + (kt + 1) * 16);
        }
        const u64*   sa = sA2 + (kt & 1) * (16 * 66);
        const float* sb = sB  + (kt & 1) * (16 * 132);
        #pragma unroll
        for (int k = 0; k < 16; k++) {
            ulonglong2 a01 = *(const ulonglong2*)(sa + k * 66 + ty * 4);
            ulonglong2 a23 = *(const ulonglong2*)(sa + k * 66 + ty * 4 + 2);
            ulonglong2 b01 = *(const ulonglong2*)(sb + k * 132 + tx * 4);
            ulonglong2 b23 = *(const ulonglong2*)(sb + k * 132 + 64 + tx * 4);
            acc[0][0] = fma2(a01.x, b01.x, acc[0][0]);
            acc[0][1] = fma2(a01.x, b01.y, acc[0][1]);
            acc[0][2] = fma2(a01.x, b23.x, acc[0][2]);
            acc[0][3] = fma2(a01.x, b23.y, acc[0][3]);
            acc[1][0] = fma2(a01.y, b01.x, acc[1][0]);
            acc[1][1] = fma2(a01.y, b01.y, acc[1][1]);
            acc[1][2] = fma2(a01.y, b23.x, acc[1][2]);
            acc[1][3] = fma2(a01.y, b23.y, acc[1][3]);
            acc[2][0] = fma2(a23.x, b01.x, acc[2][0]);
            acc[2][1] = fma2(a23.x, b01.y, acc[2][1]);
            acc[2][2] = fma2(a23.x, b23.x, acc[2][2]);
            acc[2][3] = fma2(a23.x, b23.y, acc[2][3]);
            acc[3][0] = fma2(a23.y, b01.x, acc[3][0]);
            acc[3][1] = fma2(a23.y, b01.y, acc[3][1]);
            acc[3][2] = fma2(a23.y, b23.x, acc[3][2]);
            acc[3][3] = fma2(a23.y, b23.y, acc[3][3]);
        }
        if (kt < 127) {
            u64*   sa2 = sA2 + ((kt + 1) & 1) * (16 * 66);
            float* sb2 = sB  + ((kt + 1) & 1) * (16 * 132);
            sa2[(ac4 + 0) * 66 + arow] = pack2(apf.x, apf.x);
            sa2[(ac4 + 1) * 66 + arow] = pack2(apf.y, apf.y);
            sa2[(ac4 + 2) * 66 + arow] = pack2(apf.z, apf.z);
            sa2[(ac4 + 3) * 66 + arow] = pack2(apf.w, apf.w);
            sb2[(ac4 + 0) * 132 + arow] = bpf0.x;
            sb2[(ac4 + 1) * 132 + arow] = bpf0.y;
            sb2[(ac4 + 2) * 132 + arow] = bpf0.z;
            sb2[(ac4 + 3) * 132 + arow] = bpf0.w;
            sb2[(ac4 + 0) * 132 + arow + 64] = bpf1.x;
            sb2[(ac4 + 1) * 132 + arow + 64] = bpf1.y;
            sb2[(ac4 + 2) * 132 + arow + 64] = bpf1.z;
            sb2[(ac4 + 3) * 132 + arow + 64] = bpf1.w;
        }
        __syncthreads();
    }

    // LoRA epilogue: out += U_tile(64x16) @ dB_tile(16x128)
    float* sU  = (float*)sA2;   // [64][17]
    float* sDb = sB;            // [16][132]
    {
        int row = tid >> 2, r4 = (tid & 3) * 4;
        float4 uv = *(const float4*)(U + ((size_t)b * TT + m0 + row) * ustride + uoff + r4);
        sU[row * 17 + r4 + 0] = uv.x;
        sU[row * 17 + r4 + 1] = uv.y;
        sU[row * 17 + r4 + 2] = uv.z;
        sU[row * 17 + r4 + 3] = uv.w;
        int r0 = tid >> 5, c40 = (tid & 31) * 4;
        const float* dbp = delta + ((size_t)b * 128 + dbrow) * CC + ncol0;
        *(float4*)(sDb + r0 * 132 + c40)       = *(const float4*)(dbp + (size_t)r0 * CC + c40);
        *(float4*)(sDb + (r0 + 8) * 132 + c40) = *(const float4*)(dbp + (size_t)(r0 + 8) * CC + c40);
    }
    __syncthreads();

    float o[4][8];
    #pragma unroll
    for (int i = 0; i < 4; i++)
        #pragma unroll
        for (int j = 0; j < 4; j++) {
            float2 v = unpack2(acc[i][j]);
            o[i][2 * j] = v.x; o[i][2 * j + 1] = v.y;
        }

    #pragma unroll
    for (int r = 0; r < 16; r++) {
        float4 d0 = *(const float4*)(sDb + r * 132 + tx * 4);
        float4 d1 = *(const float4*)(sDb + r * 132 + 64 + tx * 4);
        #pragma unroll
        for (int i = 0; i < 4; i++) {
            float u = sU[(ty * 4 + i) * 17 + r];
            o[i][0] += u * d0.x; o[i][1] += u * d0.y;
            o[i][2] += u * d0.z; o[i][3] += u * d0.w;
            o[i][4] += u * d1.x; o[i][5] += u * d1.y;
            o[i][6] += u * d1.z; o[i][7] += u * d1.w;
        }
    }

    if (mode == 0) {
        int seg = nbase >> 11;
        int h   = ncol0 >> 7;
        float* dst = (seg == 0) ? g_q : (seg == 1 ? g_k : g_v);
        float* base = dst + ((size_t)b * HH + h) * TT * DD;
        #pragma unroll
        for (int i = 0; i < 4; i++) {
            int t = m0 + ty * 4 + i;
            *(float4*)(base + (size_t)t * DD + tx * 4) =
                make_float4(o[i][0], o[i][1], o[i][2], o[i][3]);
            *(float4*)(base + (size_t)t * DD + 64 + tx * 4) =
                make_float4(o[i][4], o[i][5], o[i][6], o[i][7]);
        }
    } else {
        #pragma unroll
        for (int i = 0; i < 4; i++) {
            int t = m0 + ty * 4 + i;
            float* p = outO + ((size_t)b * TT + t) * CC + nbase;
            *(float4*)(p + tx * 4)      = make_float4(o[i][0], o[i][1], o[i][2], o[i][3]);
            *(float4*)(p + 64 + tx * 4) = make_float4(o[i][4], o[i][5], o[i][6], o[i][7]);
        }
    }
}

// ---------------------------------------------------------------------------
// RoPE in place on g_q, g_k (fp32 phase, matches reference).
// ---------------------------------------------------------------------------
__global__ void rope_kernel()
{
    int idx = blockIdx.x * 256 + threadIdx.x;
    if (idx >= BB * HH * TT * 64) return;
    int j  = idx & 63;
    int t  = (idx >> 6) & 1023;
    int bh = idx >> 16;
    float inv = exp2f(-(float)j * (13.2877123795f / 64.0f)); // 10000^(-j/64)
    float ang = (float)t * inv;
    float c, s;
    sincosf(ang, &s, &c);
    size_t base = ((size_t)bh * TT + t) * DD + j;
    float q1 = g_q[base], q2 = g_q[base + 64];
    g_q[base]      = q1 * c - q2 * s;
    g_q[base + 64] = q2 * c + q1 * s;
    float k1 = g_k[base], k2 = g_k[base + 64];
    g_k[base]      = k1 * c - k2 * s;
    g_k[base + 64] = k2 * c + k1 * s;
}

// ---------------------------------------------------------------------------
// Attention, flash-style online softmax. 64-query tile, 64-key tiles,
// K and V share one smem buffer. QK^T pairs along d; PV packs (p,p).
// ---------------------------------------------------------------------------
#define ATTN_SMEM_FLOATS (64 * 132 * 2 + 64 * 68 + 192)
#define ATTN_SMEM_BYTES  (ATTN_SMEM_FLOATS * 4)

__global__ __launch_bounds__(256, 2) void attn_kernel()
{
    extern __shared__ float smem[];
    float* sQ  = smem;               // [64][132]
    float* sKV = sQ + 64 * 132;      // [64][132]
    float* sS  = sKV + 64 * 132;     // [64][68]
    float* sM  = sS + 64 * 68;
    float* sL  = sM + 64;
    float* sAl = sL + 64;

    int qt = blockIdx.x, bh = blockIdx.y;
    int q0 = qt * 64;
    const float* Qb = g_q + ((size_t)bh * TT + q0) * DD;
    const float* Kb = g_k + (size_t)bh * TT * DD;
    const float* Vb = g_v + (size_t)bh * TT * DD;

    int tid = threadIdx.x, tx = tid & 15, ty = tid >> 4;

    #pragma unroll
    for (int i = 0; i < 8; i++) {
        int f = tid + i * 256, row = f >> 5, c = (f & 31) * 4;
        *(float4*)(sQ + row * 132 + c) = *(const float4*)(Qb + (size_t)row * DD + c);
    }
    if (tid < 64) { sM[tid] = -3.0e38f; sL[tid] = 0.f; }

    u64 oacc[4][4];
    #pragma unroll
    for (int i = 0; i < 4; i++)
        #pragma unroll
        for (int j = 0; j < 4; j++) oacc[i][j] = 0ULL;
    __syncthreads();

    const float scale = 0.08838834764831845f; // 1/sqrt(128)

    for (int s0 = 0; s0 < TT; s0 += 64) {
        // K tile
        #pragma unroll
        for (int i = 0; i < 8; i++) {
            int f = tid + i * 256, row = f >> 5, c = (f & 31) * 4;
            *(float4*)(sKV + row * 132 + c) = *(const float4*)(Kb + (size_t)(s0 + row) * DD + c);
        }
        __syncthreads();

        // S = Q K^T : rows ty*4+i, cols j*16+tx  (f32x2 paired along d)
        u64 acc2[4][4];
        #pragma unroll
        for (int i = 0; i < 4; i++)
            #pragma unroll
            for (int j = 0; j < 4; j++) acc2[i][j] = 0ULL;

        for (int d4 = 0; d4 < 32; d4++) {
            ulonglong2 qv[4], kv[4];
            #pragma unroll
            for (int i = 0; i < 4; i++)
                qv[i] = *(const ulonglong2*)(sQ + (ty * 4 + i) * 132 + d4 * 4);
            #pragma unroll
            for (int j = 0; j < 4; j++)
                kv[j] = *(const ulonglong2*)(sKV + (j * 16 + tx) * 132 + d4 * 4);
            #pragma unroll
            for (int i = 0; i < 4; i++)
                #pragma unroll
                for (int j = 0; j < 4; j++) {
                    acc2[i][j] = fma2(qv[i].x, kv[j].x, acc2[i][j]);
                    acc2[i][j] = fma2(qv[i].y, kv[j].y, acc2[i][j]);
                }
        }
        #pragma unroll
        for (int i = 0; i < 4; i++)
            #pragma unroll
            for (int j = 0; j < 4; j++) {
                float2 f = unpack2(acc2[i][j]);
                sS[(ty * 4 + i) * 68 + j * 16 + tx] = (f.x + f.y) * scale;
            }
        __syncthreads();   // S complete, K reads done

        // V tile (overwrites sKV) + row softmax (threads 0..63)
        #pragma unroll
        for (int i = 0; i < 8; i++) {
            int f = tid + i * 256, row = f >> 5, c = (f & 31) * 4;
            *(float4*)(sKV + row * 132 + c) = *(const float4*)(Vb + (size_t)(s0 + row) * DD + c);
        }
        if (tid < 64) {
            int r = tid;
            float m_old = sM[r], mx = m_old;
            #pragma unroll 8
            for (int c = 0; c < 64; c++) mx = fmaxf(mx, sS[r * 68 + c]);
            float alpha = __expf(m_old - mx);
            float l = sL[r] * alpha;
            #pragma unroll 8
            for (int c = 0; c < 64; c++) {
                float p = __expf(sS[r * 68 + c] - mx);
                sS[r * 68 + c] = p;
                l += p;
            }
            sM[r] = mx; sL[r] = l; sAl[r] = alpha;
        }
        __syncthreads();

        // rescale + PV : cols {tx*4..+3, 64+tx*4..+3}
        #pragma unroll
        for (int i = 0; i < 4; i++) {
            u64 a2 = pack2(sAl[ty * 4 + i], sAl[ty * 4 + i]);
            #pragma unroll
            for (int j = 0; j < 4; j++) oacc[i][j] = mul2(oacc[i][j], a2);
        }
        for (int s = 0; s < 64; s++) {
            ulonglong2 va = *(const ulonglong2*)(sKV + s * 132 + tx * 4);
            ulonglong2 vb = *(const ulonglong2*)(sKV + s * 132 + 64 + tx * 4);
            #pragma unroll
            for (int i = 0; i < 4; i++) {
                float p = sS[(ty * 4 + i) * 68 + s];
                u64 pp = pack2(p, p);
                oacc[i][0] = fma2(pp, va.x, oacc[i][0]);
                oacc[i][1] = fma2(pp, va.y, oacc[i][1]);
                oacc[i][2] = fma2(pp, vb.x, oacc[i][2]);
                oacc[i][3] = fma2(pp, vb.y, oacc[i][3]);
            }
        }
        __syncthreads();   // before next tile overwrites sKV/sS
    }

    int b = bh >> 4, h = bh & 15;
    #pragma unroll
    for (int i = 0; i < 4; i++) {
        float invl = 1.f / sL[ty * 4 + i];
        int t = q0 + ty * 4 + i;
        float* yp = g_y + ((size_t)b * TT + t) * CC + h * 128;
        float2 f0 = unpack2(oacc[i][0]);
        float2 f1 = unpack2(oacc[i][1]);
        float2 f2 = unpack2(oacc[i][2]);
        float2 f3 = unpack2(oacc[i][3]);
        *(float4*)(yp + tx * 4)      = make_float4(f0.x * invl, f0.y * invl, f1.x * invl, f1.y * invl);
        *(float4*)(yp + 64 + tx * 4) = make_float4(f2.x * invl, f2.y * invl, f3.x * invl, f3.y * invl);
    }
}

// ---------------------------------------------------------------------------
extern "C" void kernel_launch(void* const* d_in, const int* in_sizes, int n_in,
                              void* d_out, int out_size)
{
    const float* x     = (const float*)d_in[0];
    const float* delta = (const float*)d_in[1];
    const float* Wq    = (const float*)d_in[2];
    const float* Wk    = (const float*)d_in[3];
    const float* Wv    = (const float*)d_in[4];
    const float* Wo    = (const float*)d_in[5];
    float* out = (float*)d_out;

    cudaFuncSetAttribute(attn_kernel, cudaFuncAttributeMaxDynamicSharedMemorySize,
                         ATTN_SMEM_BYTES);

    lora_u_kernel<<<BB * TT, 256>>>(x, delta, 0);
    proj_kernel<<<dim3(48, 16, BB), 256>>>(x, Wq, Wk, Wv, Wo, delta, 0, nullptr);
    rope_kernel<<<(BB * HH * TT * 64) / 256, 256>>>();
    attn_kernel<<<dim3(16, BB * HH), 256, ATTN_SMEM_BYTES>>>();
    lora_u_kernel<<<BB * TT, 256>>>(x, delta, 1);
    proj_kernel<<<dim3(16, 16, BB), 256>>>(x, Wq, Wk, Wv, Wo, delta, 1, out);
}

// round 9
// speedup vs baseline: 1.8887x; 1.8887x over previous
#include <cuda_runtime.h>
#include <cuda_bf16.h>
#include <stdint.h>
#include <math.h>

#define BB 4
#define TT 1024
#define CC 2048
#define HH 16
#define DD 128

typedef unsigned long long u64;

// ===========================================================================
// f32x2 helpers (attention)
// ===========================================================================
__device__ __forceinline__ u64 fma2(u64 a, u64 b, u64 c) {
    u64 d;
    asm("fma.rn.f32x2 %0, %1, %2, %3;" : "=l"(d) : "l"(a), "l"(b), "l"(c));
    return d;
}
__device__ __forceinline__ u64 mul2(u64 a, u64 b) {
    u64 d;
    asm("mul.rn.f32x2 %0, %1, %2;" : "=l"(d) : "l"(a), "l"(b));
    return d;
}
__device__ __forceinline__ u64 pack2(float x, float y) {
    u64 d;
    asm("mov.b64 %0, {%1, %2};" : "=l"(d) : "f"(x), "f"(y));
    return d;
}
__device__ __forceinline__ float2 unpack2(u64 v) {
    float2 r;
    asm("mov.b64 {%0, %1}, %2;" : "=f"(r.x), "=f"(r.y) : "l"(v));
    return r;
}

__device__ __forceinline__ uint32_t smem_u32(const void* p) {
    uint32_t a;
    asm("{ .reg .u64 t; cvta.to.shared.u64 t, %1; cvt.u32.u64 %0, t; }" : "=r"(a) : "l"(p));
    return a;
}

// ===========================================================================
// HMMA path: ldmatrix + mma.sync (sm_80 baseline ISA)
// ===========================================================================
#define LDSM_X4(r, addr) \
    asm volatile("ldmatrix.sync.aligned.m8n8.x4.shared.b16 {%0,%1,%2,%3}, [%4];" \
        : "=r"((r)[0]), "=r"((r)[1]), "=r"((r)[2]), "=r"((r)[3]) : "r"(addr))

#define MMA_BF16(d, a, b) \
    asm volatile("mma.sync.aligned.m16n8k16.row.col.f32.bf16.bf16.f32 " \
        "{%0,%1,%2,%3}, {%4,%5,%6,%7}, {%8,%9}, {%0,%1,%2,%3};" \
        : "+f"((d)[0]), "+f"((d)[1]), "+f"((d)[2]), "+f"((d)[3]) \
        : "r"((a)[0]), "r"((a)[1]), "r"((a)[2]), "r"((a)[3]), \
          "r"((b)[0]), "r"((b)[1]))

// ===========================================================================
// Scratch (device globals — no allocation allowed)
// ===========================================================================
__device__ float g_q[8388608];   // (B,H,T,D)
__device__ float g_k[8388608];
__device__ float g_v[8388608];
__device__ float g_y[8388608];   // (B,T,C)
__device__ float g_u[196608];    // (B,T,48)
__device__ float g_uo[65536];    // (B,T,16)
__device__ __align__(16) __nv_bfloat16 g_xhi[8388608];
__device__ __align__(16) __nv_bfloat16 g_xlo[8388608];
__device__ __align__(16) __nv_bfloat16 g_yhi[8388608];
__device__ __align__(16) __nv_bfloat16 g_ylo[8388608];
__device__ __align__(16) __nv_bfloat16 g_whi[16777216];  // [q|k|v|o][2048][2048]
__device__ __align__(16) __nv_bfloat16 g_wlo[16777216];

// ===========================================================================
// fp32 -> bf16 hi/lo split kernels (all outputs are device globals)
// ===========================================================================
__device__ __forceinline__ void split4(float4 v, __nv_bfloat16* hi, __nv_bfloat16* lo) {
    __nv_bfloat16 h0 = __float2bfloat16(v.x), h1 = __float2bfloat16(v.y);
    __nv_bfloat16 h2 = __float2bfloat16(v.z), h3 = __float2bfloat16(v.w);
    __nv_bfloat16 l0 = __float2bfloat16(v.x - __bfloat162float(h0));
    __nv_bfloat16 l1 = __float2bfloat16(v.y - __bfloat162float(h1));
    __nv_bfloat16 l2 = __float2bfloat16(v.z - __bfloat162float(h2));
    __nv_bfloat16 l3 = __float2bfloat16(v.w - __bfloat162float(h3));
    __nv_bfloat162 p;
    p.x = h0; p.y = h1; *(__nv_bfloat162*)(hi)     = p;
    p.x = h2; p.y = h3; *(__nv_bfloat162*)(hi + 2) = p;
    p.x = l0; p.y = l1; *(__nv_bfloat162*)(lo)     = p;
    p.x = l2; p.y = l3; *(__nv_bfloat162*)(lo + 2) = p;
}

// mode 0: split x -> g_xhi/g_xlo.  mode 1: split g_y -> g_yhi/g_ylo.
__global__ void split_xy_kernel(const float* __restrict__ x, int mode)
{
    int i = (blockIdx.x * 256 + threadIdx.x) * 4;
    const float* src = (mode == 0) ? x : (const float*)g_y;
    __nv_bfloat16* hi = (mode == 0) ? g_xhi : g_yhi;
    __nv_bfloat16* lo = (mode == 0) ? g_xlo : g_ylo;
    split4(*(const float4*)(src + i), hi + i, lo + i);
}

__global__ void split_w_kernel(const float* __restrict__ Wq, const float* __restrict__ Wk,
                               const float* __restrict__ Wv, const float* __restrict__ Wo)
{
    int j = blockIdx.y;
    const float* src = (j == 0) ? Wq : (j == 1) ? Wk : (j == 2) ? Wv : Wo;
    size_t base = (size_t)j * 4194304;
    int i = (blockIdx.x * 256 + threadIdx.x) * 4;
    split4(*(const float4*)(src + i), g_whi + base + i, g_wlo + base + i);
}

// ===========================================================================
// LoRA left factor. mode 0: U = x @ dA^T (48 cols), mode 1: Uo = y @ doA^T
// ===========================================================================
__global__ void lora_u_kernel(const float* __restrict__ x,
                              const float* __restrict__ delta, int mode)
{
    int bt = blockIdx.x;
    int b  = bt >> 10;
    const float* src  = (mode == 0) ? x : (const float*)g_y;
    const float* xrow = src + (size_t)bt * CC;
    float* dst = (mode == 0) ? g_u : g_uo;
    int nOut   = (mode == 0) ? 48 : 16;

    int lane = threadIdx.x & 31, w = threadIdx.x >> 5;
    for (int j = w; j < nOut; j += 8) {
        int row = (mode == 0) ? ((j >> 4) * 32 + (j & 15)) : (96 + j);
        const float* arow = delta + ((size_t)b * 128 + row) * CC;
        float s = 0.f;
        for (int i = lane * 4; i < CC; i += 128) {
            float4 xv = *(const float4*)(xrow + i);
            float4 av = *(const float4*)(arow + i);
            s += xv.x * av.x + xv.y * av.y + xv.z * av.z + xv.w * av.w;
        }
        #pragma unroll
        for (int o = 16; o; o >>= 1) s += __shfl_xor_sync(0xffffffffu, s, o);
        if (lane == 0) dst[(size_t)bt * nOut + j] = s;
    }
}

// ===========================================================================
// bf16x3 GEMM on mma.sync (HMMA). Tile 128(M) x 128(N), K-stage 32,
// 8 warps (2m x 4n), warp tile 64x32. Smem rows padded to 80B.
// mode 0: QKV from g_xhi/g_xlo, head-layout out. mode 1: O from g_yhi/g_ylo.
// ===========================================================================
#define MMH_STAGE 40960
#define MMH_SMEM  (2 * MMH_STAGE)

__global__ __launch_bounds__(256, 1)
void mmh_kernel(const float* __restrict__ delta, int mode, float* __restrict__ outO)
{
    extern __shared__ __align__(16) char sm[];
    const int tid = threadIdx.x, lane = tid & 31, wid = tid >> 5;
    const int wm = wid >> 2, wn = wid & 3;
    const int b = blockIdx.z, mt = blockIdx.y, nt = blockIdx.x;
    const int m0 = mt * 128, nbase = nt * 128;
    const int wrow0 = (mode == 0) ? nbase : (6144 + nbase);
    const size_t arow0 = (size_t)b * 1024 + m0;

    const __nv_bfloat16* Ahi = (mode == 0) ? g_xhi : g_yhi;
    const __nv_bfloat16* Alo = (mode == 0) ? g_xlo : g_ylo;
    const float* Uv = (mode == 0) ? g_u : g_uo;

    const int r0 = tid >> 2, s0 = tid & 3;
    const int r1 = r0 + 64;
    const __nv_bfloat16* gAh0 = Ahi + (arow0 + r0) * 2048 + s0 * 8;
    const __nv_bfloat16* gAh1 = Ahi + (arow0 + r1) * 2048 + s0 * 8;
    const __nv_bfloat16* gAl0 = Alo + (arow0 + r0) * 2048 + s0 * 8;
    const __nv_bfloat16* gAl1 = Alo + (arow0 + r1) * 2048 + s0 * 8;
    const __nv_bfloat16* gBh0 = g_whi + (size_t)(wrow0 + r0) * 2048 + s0 * 8;
    const __nv_bfloat16* gBh1 = g_whi + (size_t)(wrow0 + r1) * 2048 + s0 * 8;
    const __nv_bfloat16* gBl0 = g_wlo + (size_t)(wrow0 + r0) * 2048 + s0 * 8;
    const __nv_bfloat16* gBl1 = g_wlo + (size_t)(wrow0 + r1) * 2048 + s0 * 8;
    const uint32_t so0 = (uint32_t)r0 * 80 + s0 * 16;
    const uint32_t so1 = (uint32_t)r1 * 80 + s0 * 16;

    float acc[4][4][4];
    #pragma unroll
    for (int mi = 0; mi < 4; mi++)
        #pragma unroll
        for (int ni = 0; ni < 4; ni++)
            #pragma unroll
            for (int e = 0; e < 4; e++) acc[mi][ni][e] = 0.f;

    {
        char* s0b = sm;
        *(uint4*)(s0b + so0)         = *(const uint4*)gAh0;
        *(uint4*)(s0b + so1)         = *(const uint4*)gAh1;
        *(uint4*)(s0b + 10240 + so0) = *(const uint4*)gAl0;
        *(uint4*)(s0b + 10240 + so1) = *(const uint4*)gAl1;
        *(uint4*)(s0b + 20480 + so0) = *(const uint4*)gBh0;
        *(uint4*)(s0b + 20480 + so1) = *(const uint4*)gBh1;
        *(uint4*)(s0b + 30720 + so0) = *(const uint4*)gBl0;
        *(uint4*)(s0b + 30720 + so1) = *(const uint4*)gBl1;
    }
    __syncthreads();

    const uint32_t aRowBase = (uint32_t)(wm * 64 + (lane & 15)) * 80 + (lane >> 4) * 16;
    const uint32_t bRowBase = (uint32_t)(wn * 32 + (lane & 15)) * 80 + (lane >> 4) * 16;

    for (int kt = 0; kt < 64; kt++) {
        uint4 qa0, qa1, ql0, ql1, qb0, qb1, qm0, qm1;
        if (kt < 63) {
            int kk = (kt + 1) * 32;
            qa0 = *(const uint4*)(gAh0 + kk);
            qa1 = *(const uint4*)(gAh1 + kk);
            ql0 = *(const uint4*)(gAl0 + kk);
            ql1 = *(const uint4*)(gAl1 + kk);
            qb0 = *(const uint4*)(gBh0 + kk);
            qb1 = *(const uint4*)(gBh1 + kk);
            qm0 = *(const uint4*)(gBl0 + kk);
            qm1 = *(const uint4*)(gBl1 + kk);
        }
        uint32_t sA = smem_u32(sm + (kt & 1) * MMH_STAGE);
        uint32_t sB = sA + 20480;
        #pragma unroll
        for (int ks = 0; ks < 2; ks++) {
            uint32_t ah[4][4], al[4][4], bh[4][2], bl[4][2];
            #pragma unroll
            for (int mi = 0; mi < 4; mi++) {
                uint32_t ad = sA + aRowBase + mi * (16 * 80) + ks * 32;
                LDSM_X4(ah[mi], ad);
                LDSM_X4(al[mi], ad + 10240);
            }
            #pragma unroll
            for (int g = 0; g < 2; g++) {
                uint32_t bd = sB + bRowBase + g * (16 * 80) + ks * 32;
                uint32_t t[4], tl[4];
                LDSM_X4(t, bd);
                LDSM_X4(tl, bd + 10240);
                bh[g * 2][0] = t[0];  bh[g * 2][1] = t[2];
                bh[g * 2 + 1][0] = t[1]; bh[g * 2 + 1][1] = t[3];
                bl[g * 2][0] = tl[0]; bl[g * 2][1] = tl[2];
                bl[g * 2 + 1][0] = tl[1]; bl[g * 2 + 1][1] = tl[3];
            }
            #pragma unroll
            for (int mi = 0; mi < 4; mi++)
                #pragma unroll
                for (int ni = 0; ni < 4; ni++) {
                    MMA_BF16(acc[mi][ni], ah[mi], bh[ni]);
                    MMA_BF16(acc[mi][ni], al[mi], bh[ni]);
                    MMA_BF16(acc[mi][ni], ah[mi], bl[ni]);
                }
        }
        if (kt < 63) {
            char* nx = sm + ((kt + 1) & 1) * MMH_STAGE;
            *(uint4*)(nx + so0)         = qa0;
            *(uint4*)(nx + so1)         = qa1;
            *(uint4*)(nx + 10240 + so0) = ql0;
            *(uint4*)(nx + 10240 + so1) = ql1;
            *(uint4*)(nx + 20480 + so0) = qb0;
            *(uint4*)(nx + 20480 + so1) = qb1;
            *(uint4*)(nx + 30720 + so0) = qm0;
            *(uint4*)(nx + 30720 + so1) = qm1;
        }
        __syncthreads();
    }

    // ---- LoRA epilogue + writeback ----
    float* sU  = (float*)sm;               // [128][17]
    float* sDb = (float*)(sm + 12288);     // [16][136]
    const int seg     = (mode == 0) ? (nbase >> 11) : 3;
    const int ncol0   = (mode == 0) ? (nbase & 2047) : nbase;
    const int dbrow   = (mode == 0) ? (seg * 32 + 16) : 112;
    const int ustride = (mode == 0) ? 48 : 16;
    const int uoff    = (mode == 0) ? seg * 16 : 0;

    if (tid < 128) {
        const float* up = Uv + ((size_t)b * 1024 + m0 + tid) * ustride + uoff;
        #pragma unroll
        for (int i = 0; i < 4; i++) {
            float4 v = *(const float4*)(up + i * 4);
            sU[tid * 17 + i * 4 + 0] = v.x;
            sU[tid * 17 + i * 4 + 1] = v.y;
            sU[tid * 17 + i * 4 + 2] = v.z;
            sU[tid * 17 + i * 4 + 3] = v.w;
        }
    }
    #pragma unroll
    for (int i = 0; i < 2; i++) {
        int u = tid + i * 256;
        int r = u >> 5, c4 = (u & 31) * 4;
        float4 v = *(const float4*)(delta + ((size_t)b * 128 + dbrow + r) * 2048 + ncol0 + c4);
        *(float4*)(sDb + r * 136 + c4) = v;
    }
    __syncthreads();

    const int trow = lane >> 2;
    const int tcol = (lane & 3) * 2;
    float* qkvbase = (seg == 0) ? g_q : (seg == 1) ? g_k : g_v;

    #pragma unroll
    for (int mi = 0; mi < 4; mi++) {
        int lr0 = wm * 64 + mi * 16 + trow;
        int lr1 = lr0 + 8;
        #pragma unroll
        for (int r = 0; r < 16; r++) {
            float u0 = sU[lr0 * 17 + r];
            float u1 = sU[lr1 * 17 + r];
            #pragma unroll
            for (int ni = 0; ni < 4; ni++) {
                int c = wn * 32 + ni * 8 + tcol;
                float d0 = sDb[r * 136 + c];
                float d1 = sDb[r * 136 + c + 1];
                acc[mi][ni][0] += u0 * d0;
                acc[mi][ni][1] += u0 * d1;
                acc[mi][ni][2] += u1 * d0;
                acc[mi][ni][3] += u1 * d1;
            }
        }
        #pragma unroll
        for (int ni = 0; ni < 4; ni++) {
            int c = wn * 32 + ni * 8 + tcol;
            if (mode == 0) {
                int h = ncol0 >> 7;
                float* dst = qkvbase + (((size_t)b * 16 + h) * 1024 + m0) * 128;
                *(float2*)(dst + (size_t)lr0 * 128 + c) = make_float2(acc[mi][ni][0], acc[mi][ni][1]);
                *(float2*)(dst + (size_t)lr1 * 128 + c) = make_float2(acc[mi][ni][2], acc[mi][ni][3]);
            } else {
                float* dst = outO + ((size_t)b * 1024 + m0) * 2048 + nbase;
                *(float2*)(dst + (size_t)lr0 * 2048 + c) = make_float2(acc[mi][ni][0], acc[mi][ni][1]);
                *(float2*)(dst + (size_t)lr1 * 2048 + c) = make_float2(acc[mi][ni][2], acc[mi][ni][3]);
            }
        }
    }
}

// ===========================================================================
// RoPE in place on g_q, g_k
// ===========================================================================
__global__ void rope_kernel()
{
    int idx = blockIdx.x * 256 + threadIdx.x;
    if (idx >= BB * HH * TT * 64) return;
    int j  = idx & 63;
    int t  = (idx >> 6) & 1023;
    int bh = idx >> 16;
    float inv = exp2f(-(float)j * (13.2877123795f / 64.0f));
    float ang = (float)t * inv;
    float c, s;
    sincosf(ang, &s, &c);
    size_t base = ((size_t)bh * TT + t) * DD + j;
    float q1 = g_q[base], q2 = g_q[base + 64];
    g_q[base]      = q1 * c - q2 * s;
    g_q[base + 64] = q2 * c + q1 * s;
    float k1 = g_k[base], k2 = g_k[base + 64];
    g_k[base]      = k1 * c - k2 * s;
    g_k[base + 64] = k2 * c + k1 * s;
}

// ===========================================================================
// Attention (passing round-2 kernel, unchanged)
// ===========================================================================
#define ATTN_SMEM_FLOATS (64 * 132 * 2 + 64 * 68 + 192)
#define ATTN_SMEM_BYTES  (ATTN_SMEM_FLOATS * 4)

__global__ __launch_bounds__(256, 2) void attn_kernel()
{
    extern __shared__ float smemf[];
    float* sQ  = smemf;
    float* sKV = sQ + 64 * 132;
    float* sS  = sKV + 64 * 132;
    float* sM  = sS + 64 * 68;
    float* sL  = sM + 64;
    float* sAl = sL + 64;

    int qt = blockIdx.x, bh = blockIdx.y;
    int q0 = qt * 64;
    const float* Qb = g_q + ((size_t)bh * TT + q0) * DD;
    const float* Kb = g_k + (size_t)bh * TT * DD;
    const float* Vb = g_v + (size_t)bh * TT * DD;

    int tid = threadIdx.x, tx = tid & 15, ty = tid >> 4;

    #pragma unroll
    for (int i = 0; i < 8; i++) {
        int f = tid + i * 256, row = f >> 5, c = (f & 31) * 4;
        *(float4*)(sQ + row * 132 + c) = *(const float4*)(Qb + (size_t)row * DD + c);
    }
    if (tid < 64) { sM[tid] = -3.0e38f; sL[tid] = 0.f; }

    u64 oacc[4][4];
    #pragma unroll
    for (int i = 0; i < 4; i++)
        #pragma unroll
        for (int j = 0; j < 4; j++) oacc[i][j] = 0ULL;
    __syncthreads();

    const float scale = 0.08838834764831845f;

    for (int s0 = 0; s0 < TT; s0 += 64) {
        #pragma unroll
        for (int i = 0; i < 8; i++) {
            int f = tid + i * 256, row = f >> 5, c = (f & 31) * 4;
            *(float4*)(sKV + row * 132 + c) = *(const float4*)(Kb + (size_t)(s0 + row) * DD + c);
        }
        __syncthreads();

        u64 acc2[4][4];
        #pragma unroll
        for (int i = 0; i < 4; i++)
            #pragma unroll
            for (int j = 0; j < 4; j++) acc2[i][j] = 0ULL;

        for (int d4 = 0; d4 < 32; d4++) {
            ulonglong2 qv[4], kv[4];
            #pragma unroll
            for (int i = 0; i < 4; i++)
                qv[i] = *(const ulonglong2*)(sQ + (ty * 4 + i) * 132 + d4 * 4);
            #pragma unroll
            for (int j = 0; j < 4; j++)
                kv[j] = *(const ulonglong2*)(sKV + (j * 16 + tx) * 132 + d4 * 4);
            #pragma unroll
            for (int i = 0; i < 4; i++)
                #pragma unroll
                for (int j = 0; j < 4; j++) {
                    acc2[i][j] = fma2(qv[i].x, kv[j].x, acc2[i][j]);
                    acc2[i][j] = fma2(qv[i].y, kv[j].y, acc2[i][j]);
                }
        }
        #pragma unroll
        for (int i = 0; i < 4; i++)
            #pragma unroll
            for (int j = 0; j < 4; j++) {
                float2 f = unpack2(acc2[i][j]);
                sS[(ty * 4 + i) * 68 + j * 16 + tx] = (f.x + f.y) * scale;
            }
        __syncthreads();

        #pragma unroll
        for (int i = 0; i < 8; i++) {
            int f = tid + i * 256, row = f >> 5, c = (f & 31) * 4;
            *(float4*)(sKV + row * 132 + c) = *(const float4*)(Vb + (size_t)(s0 + row) * DD + c);
        }
        if (tid < 64) {
            int r = tid;
            float m_old = sM[r], mx = m_old;
            #pragma unroll 8
            for (int c = 0; c < 64; c++) mx = fmaxf(mx, sS[r * 68 + c]);
            float alpha = __expf(m_old - mx);
            float l = sL[r] * alpha;
            #pragma unroll 8
            for (int c = 0; c < 64; c++) {
                float p = __expf(sS[r * 68 + c] - mx);
                sS[r * 68 + c] = p;
                l += p;
            }
            sM[r] = mx; sL[r] = l; sAl[r] = alpha;
        }
        __syncthreads();

        #pragma unroll
        for (int i = 0; i < 4; i++) {
            u64 a2 = pack2(sAl[ty * 4 + i], sAl[ty * 4 + i]);
            #pragma unroll
            for (int j = 0; j < 4; j++) oacc[i][j] = mul2(oacc[i][j], a2);
        }
        for (int s = 0; s < 64; s++) {
            ulonglong2 va = *(const ulonglong2*)(sKV + s * 132 + tx * 4);
            ulonglong2 vb = *(const ulonglong2*)(sKV + s * 132 + 64 + tx * 4);
            #pragma unroll
            for (int i = 0; i < 4; i++) {
                float p = sS[(ty * 4 + i) * 68 + s];
                u64 pp = pack2(p, p);
                oacc[i][0] = fma2(pp, va.x, oacc[i][0]);
                oacc[i][1] = fma2(pp, va.y, oacc[i][1]);
                oacc[i][2] = fma2(pp, vb.x, oacc[i][2]);
                oacc[i][3] = fma2(pp, vb.y, oacc[i][3]);
            }
        }
        __syncthreads();
    }

    int b = bh >> 4, h = bh & 15;
    #pragma unroll
    for (int i = 0; i < 4; i++) {
        float invl = 1.f / sL[ty * 4 + i];
        int t = q0 + ty * 4 + i;
        float* yp = g_y + ((size_t)b * TT + t) * CC + h * 128;
        float2 f0 = unpack2(oacc[i][0]);
        float2 f1 = unpack2(oacc[i][1]);
        float2 f2 = unpack2(oacc[i][2]);
        float2 f3 = unpack2(oacc[i][3]);
        *(float4*)(yp + tx * 4)      = make_float4(f0.x * invl, f0.y * invl, f1.x * invl, f1.y * invl);
        *(float4*)(yp + 64 + tx * 4) = make_float4(f2.x * invl, f2.y * invl, f3.x * invl, f3.y * invl);
    }
}

// ===========================================================================
extern "C" void kernel_launch(void* const* d_in, const int* in_sizes, int n_in,
                              void* d_out, int out_size)
{
    const float* x     = (const float*)d_in[0];
    const float* delta = (const float*)d_in[1];
    const float* Wq    = (const float*)d_in[2];
    const float* Wk    = (const float*)d_in[3];
    const float* Wv    = (const float*)d_in[4];
    const float* Wo    = (const float*)d_in[5];
    float* out = (float*)d_out;

    cudaFuncSetAttribute(attn_kernel, cudaFuncAttributeMaxDynamicSharedMemorySize,
                         ATTN_SMEM_BYTES);
    cudaFuncSetAttribute(mmh_kernel, cudaFuncAttributeMaxDynamicSharedMemorySize,
                         MMH_SMEM);

    split_w_kernel<<<dim3(4096, 4), 256>>>(Wq, Wk, Wv, Wo);
    split_xy_kernel<<<8192, 256>>>(x, 0);
    lora_u_kernel<<<BB * TT, 256>>>(x, delta, 0);
    mmh_kernel<<<dim3(48, 8, BB), 256, MMH_SMEM>>>(delta, 0, nullptr);
    rope_kernel<<<(BB * HH * TT * 64) / 256, 256>>>();
    attn_kernel<<<dim3(16, BB * HH), 256, ATTN_SMEM_BYTES>>>();
    lora_u_kernel<<<BB * TT, 256>>>(x, delta, 1);
    split_xy_kernel<<<8192, 256>>>(x, 1);
    mmh_kernel<<<dim3(16, 8, BB), 256, MMH_SMEM>>>(delta, 1, out);
}

// round 10
// speedup vs baseline: 2.2995x; 1.2175x over previous
#include <cuda_runtime.h>
#include <cuda_bf16.h>
#include <stdint.h>
#include <math.h>

#define BB 4
#define TT 1024
#define CC 2048
#define HH 16
#define DD 128

typedef unsigned long long u64;

__device__ __forceinline__ uint32_t smem_u32(const void* p) {
    uint32_t a;
    asm("{ .reg .u64 t; cvta.to.shared.u64 t, %1; cvt.u32.u64 %0, t; }" : "=r"(a) : "l"(p));
    return a;
}

// ===========================================================================
// HMMA path: ldmatrix + mma.sync (sm_80 baseline ISA)
// ===========================================================================
#define LDSM_X4(r, addr) \
    asm volatile("ldmatrix.sync.aligned.m8n8.x4.shared.b16 {%0,%1,%2,%3}, [%4];" \
        : "=r"((r)[0]), "=r"((r)[1]), "=r"((r)[2]), "=r"((r)[3]) : "r"(addr))

#define LDSM_X4_T(r, addr) \
    asm volatile("ldmatrix.sync.aligned.m8n8.x4.trans.shared.b16 {%0,%1,%2,%3}, [%4];" \
        : "=r"((r)[0]), "=r"((r)[1]), "=r"((r)[2]), "=r"((r)[3]) : "r"(addr))

#define MMA_BF16(d, a, b) \
    asm volatile("mma.sync.aligned.m16n8k16.row.col.f32.bf16.bf16.f32 " \
        "{%0,%1,%2,%3}, {%4,%5,%6,%7}, {%8,%9}, {%0,%1,%2,%3};" \
        : "+f"((d)[0]), "+f"((d)[1]), "+f"((d)[2]), "+f"((d)[3]) \
        : "r"((a)[0]), "r"((a)[1]), "r"((a)[2]), "r"((a)[3]), \
          "r"((b)[0]), "r"((b)[1]))

// ===========================================================================
// Scratch (device globals — no allocation allowed)
// ===========================================================================
__device__ float g_q[8388608];   // (B,H,T,D)
__device__ float g_k[8388608];
__device__ float g_v[8388608];
__device__ float g_y[8388608];   // (B,T,C)
__device__ float g_u[196608];    // (B,T,48)
__device__ float g_uo[65536];    // (B,T,16)
__device__ __align__(16) __nv_bfloat16 g_xhi[8388608];
__device__ __align__(16) __nv_bfloat16 g_xlo[8388608];
__device__ __align__(16) __nv_bfloat16 g_yhi[8388608];
__device__ __align__(16) __nv_bfloat16 g_ylo[8388608];
__device__ __align__(16) __nv_bfloat16 g_whi[16777216];  // [q|k|v|o][2048][2048]
__device__ __align__(16) __nv_bfloat16 g_wlo[16777216];
__device__ __align__(16) __nv_bfloat16 g_qhi[8388608];
__device__ __align__(16) __nv_bfloat16 g_qlo[8388608];
__device__ __align__(16) __nv_bfloat16 g_khi[8388608];
__device__ __align__(16) __nv_bfloat16 g_klo[8388608];
__device__ __align__(16) __nv_bfloat16 g_vhi[8388608];
__device__ __align__(16) __nv_bfloat16 g_vlo[8388608];

// ===========================================================================
// fp32 -> bf16 hi/lo split kernels (all outputs are device globals)
// ===========================================================================
__device__ __forceinline__ void split4(float4 v, __nv_bfloat16* hi, __nv_bfloat16* lo) {
    __nv_bfloat16 h0 = __float2bfloat16(v.x), h1 = __float2bfloat16(v.y);
    __nv_bfloat16 h2 = __float2bfloat16(v.z), h3 = __float2bfloat16(v.w);
    __nv_bfloat16 l0 = __float2bfloat16(v.x - __bfloat162float(h0));
    __nv_bfloat16 l1 = __float2bfloat16(v.y - __bfloat162float(h1));
    __nv_bfloat16 l2 = __float2bfloat16(v.z - __bfloat162float(h2));
    __nv_bfloat16 l3 = __float2bfloat16(v.w - __bfloat162float(h3));
    __nv_bfloat162 p;
    p.x = h0; p.y = h1; *(__nv_bfloat162*)(hi)     = p;
    p.x = h2; p.y = h3; *(__nv_bfloat162*)(hi + 2) = p;
    p.x = l0; p.y = l1; *(__nv_bfloat162*)(lo)     = p;
    p.x = l2; p.y = l3; *(__nv_bfloat162*)(lo + 2) = p;
}

// mode 0: split x -> g_xhi/g_xlo.  mode 1: split g_y -> g_yhi/g_ylo.
__global__ void split_xy_kernel(const float* __restrict__ x, int mode)
{
    int i = (blockIdx.x * 256 + threadIdx.x) * 4;
    const float* src = (mode == 0) ? x : (const float*)g_y;
    __nv_bfloat16* hi = (mode == 0) ? g_xhi : g_yhi;
    __nv_bfloat16* lo = (mode == 0) ? g_xlo : g_ylo;
    split4(*(const float4*)(src + i), hi + i, lo + i);
}

__global__ void split_w_kernel(const float* __restrict__ Wq, const float* __restrict__ Wk,
                               const float* __restrict__ Wv, const float* __restrict__ Wo)
{
    int j = blockIdx.y;
    const float* src = (j == 0) ? Wq : (j == 1) ? Wk : (j == 2) ? Wv : Wo;
    size_t base = (size_t)j * 4194304;
    int i = (blockIdx.x * 256 + threadIdx.x) * 4;
    split4(*(const float4*)(src + i), g_whi + base + i, g_wlo + base + i);
}

// split rope'd q,k and plain v into bf16 hi/lo
__global__ void split_qkv_kernel()
{
    int j = blockIdx.y;
    const float* src = (j == 0) ? g_q : (j == 1) ? g_k : g_v;
    __nv_bfloat16* hi = (j == 0) ? g_qhi : (j == 1) ? g_khi : g_vhi;
    __nv_bfloat16* lo = (j == 0) ? g_qlo : (j == 1) ? g_klo : g_vlo;
    int i = (blockIdx.x * 256 + threadIdx.x) * 4;
    split4(*(const float4*)(src + i), hi + i, lo + i);
}

// ===========================================================================
// LoRA left factor. mode 0: U = x @ dA^T (48 cols), mode 1: Uo = y @ doA^T
// ===========================================================================
__global__ void lora_u_kernel(const float* __restrict__ x,
                              const float* __restrict__ delta, int mode)
{
    int bt = blockIdx.x;
    int b  = bt >> 10;
    const float* src  = (mode == 0) ? x : (const float*)g_y;
    const float* xrow = src + (size_t)bt * CC;
    float* dst = (mode == 0) ? g_u : g_uo;
    int nOut   = (mode == 0) ? 48 : 16;

    int lane = threadIdx.x & 31, w = threadIdx.x >> 5;
    for (int j = w; j < nOut; j += 8) {
        int row = (mode == 0) ? ((j >> 4) * 32 + (j & 15)) : (96 + j);
        const float* arow = delta + ((size_t)b * 128 + row) * CC;
        float s = 0.f;
        for (int i = lane * 4; i < CC; i += 128) {
            float4 xv = *(const float4*)(xrow + i);
            float4 av = *(const float4*)(arow + i);
            s += xv.x * av.x + xv.y * av.y + xv.z * av.z + xv.w * av.w;
        }
        #pragma unroll
        for (int o = 16; o; o >>= 1) s += __shfl_xor_sync(0xffffffffu, s, o);
        if (lane == 0) dst[(size_t)bt * nOut + j] = s;
    }
}

// ===========================================================================
// bf16x3 GEMM on mma.sync (HMMA). Tile 128(M) x 128(N), K-stage 32,
// 8 warps (2m x 4n), warp tile 64x32. Smem rows padded to 80B.
// mode 0: QKV from g_xhi/g_xlo, head-layout out. mode 1: O from g_yhi/g_ylo.
// ===========================================================================
#define MMH_STAGE 40960
#define MMH_SMEM  (2 * MMH_STAGE)

__global__ __launch_bounds__(256, 1)
void mmh_kernel(const float* __restrict__ delta, int mode, float* __restrict__ outO)
{
    extern __shared__ __align__(16) char sm[];
    const int tid = threadIdx.x, lane = tid & 31, wid = tid >> 5;
    const int wm = wid >> 2, wn = wid & 3;
    const int b = blockIdx.z, mt = blockIdx.y, nt = blockIdx.x;
    const int m0 = mt * 128, nbase = nt * 128;
    const int wrow0 = (mode == 0) ? nbase : (6144 + nbase);
    const size_t arow0 = (size_t)b * 1024 + m0;

    const __nv_bfloat16* Ahi = (mode == 0) ? g_xhi : g_yhi;
    const __nv_bfloat16* Alo = (mode == 0) ? g_xlo : g_ylo;
    const float* Uv = (mode == 0) ? g_u : g_uo;

    const int r0 = tid >> 2, s0 = tid & 3;
    const int r1 = r0 + 64;
    const __nv_bfloat16* gAh0 = Ahi + (arow0 + r0) * 2048 + s0 * 8;
    const __nv_bfloat16* gAh1 = Ahi + (arow0 + r1) * 2048 + s0 * 8;
    const __nv_bfloat16* gAl0 = Alo + (arow0 + r0) * 2048 + s0 * 8;
    const __nv_bfloat16* gAl1 = Alo + (arow0 + r1) * 2048 + s0 * 8;
    const __nv_bfloat16* gBh0 = g_whi + (size_t)(wrow0 + r0) * 2048 + s0 * 8;
    const __nv_bfloat16* gBh1 = g_whi + (size_t)(wrow0 + r1) * 2048 + s0 * 8;
    const __nv_bfloat16* gBl0 = g_wlo + (size_t)(wrow0 + r0) * 2048 + s0 * 8;
    const __nv_bfloat16* gBl1 = g_wlo + (size_t)(wrow0 + r1) * 2048 + s0 * 8;
    const uint32_t so0 = (uint32_t)r0 * 80 + s0 * 16;
    const uint32_t so1 = (uint32_t)r1 * 80 + s0 * 16;

    float acc[4][4][4];
    #pragma unroll
    for (int mi = 0; mi < 4; mi++)
        #pragma unroll
        for (int ni = 0; ni < 4; ni++)
            #pragma unroll
            for (int e = 0; e < 4; e++) acc[mi][ni][e] = 0.f;

    {
        char* s0b = sm;
        *(uint4*)(s0b + so0)         = *(const uint4*)gAh0;
        *(uint4*)(s0b + so1)         = *(const uint4*)gAh1;
        *(uint4*)(s0b + 10240 + so0) = *(const uint4*)gAl0;
        *(uint4*)(s0b + 10240 + so1) = *(const uint4*)gAl1;
        *(uint4*)(s0b + 20480 + so0) = *(const uint4*)gBh0;
        *(uint4*)(s0b + 20480 + so1) = *(const uint4*)gBh1;
        *(uint4*)(s0b + 30720 + so0) = *(const uint4*)gBl0;
        *(uint4*)(s0b + 30720 + so1) = *(const uint4*)gBl1;
    }
    __syncthreads();

    const uint32_t aRowBase = (uint32_t)(wm * 64 + (lane & 15)) * 80 + (lane >> 4) * 16;
    const uint32_t bRowBase = (uint32_t)(wn * 32 + (lane & 15)) * 80 + (lane >> 4) * 16;

    for (int kt = 0; kt < 64; kt++) {
        uint4 qa0, qa1, ql0, ql1, qb0, qb1, qm0, qm1;
        if (kt < 63) {
            int kk = (kt + 1) * 32;
            qa0 = *(const uint4*)(gAh0 + kk);
            qa1 = *(const uint4*)(gAh1 + kk);
            ql0 = *(const uint4*)(gAl0 + kk);
            ql1 = *(const uint4*)(gAl1 + kk);
            qb0 = *(const uint4*)(gBh0 + kk);
            qb1 = *(const uint4*)(gBh1 + kk);
            qm0 = *(const uint4*)(gBl0 + kk);
            qm1 = *(const uint4*)(gBl1 + kk);
        }
        uint32_t sA = smem_u32(sm + (kt & 1) * MMH_STAGE);
        uint32_t sB = sA + 20480;
        #pragma unroll
        for (int ks = 0; ks < 2; ks++) {
            uint32_t ah[4][4], al[4][4], bh[4][2], bl[4][2];
            #pragma unroll
            for (int mi = 0; mi < 4; mi++) {
                uint32_t ad = sA + aRowBase + mi * (16 * 80) + ks * 32;
                LDSM_X4(ah[mi], ad);
                LDSM_X4(al[mi], ad + 10240);
            }
            #pragma unroll
            for (int g = 0; g < 2; g++) {
                uint32_t bd = sB + bRowBase + g * (16 * 80) + ks * 32;
                uint32_t t[4], tl[4];
                LDSM_X4(t, bd);
                LDSM_X4(tl, bd + 10240);
                bh[g * 2][0] = t[0];  bh[g * 2][1] = t[2];
                bh[g * 2 + 1][0] = t[1]; bh[g * 2 + 1][1] = t[3];
                bl[g * 2][0] = tl[0]; bl[g * 2][1] = tl[2];
                bl[g * 2 + 1][0] = tl[1]; bl[g * 2 + 1][1] = tl[3];
            }
            #pragma unroll
            for (int mi = 0; mi < 4; mi++)
                #pragma unroll
                for (int ni = 0; ni < 4; ni++) {
                    MMA_BF16(acc[mi][ni], ah[mi], bh[ni]);
                    MMA_BF16(acc[mi][ni], al[mi], bh[ni]);
                    MMA_BF16(acc[mi][ni], ah[mi], bl[ni]);
                }
        }
        if (kt < 63) {
            char* nx = sm + ((kt + 1) & 1) * MMH_STAGE;
            *(uint4*)(nx + so0)         = qa0;
            *(uint4*)(nx + so1)         = qa1;
            *(uint4*)(nx + 10240 + so0) = ql0;
            *(uint4*)(nx + 10240 + so1) = ql1;
            *(uint4*)(nx + 20480 + so0) = qb0;
            *(uint4*)(nx + 20480 + so1) = qb1;
            *(uint4*)(nx + 30720 + so0) = qm0;
            *(uint4*)(nx + 30720 + so1) = qm1;
        }
        __syncthreads();
    }

    // ---- LoRA epilogue + writeback ----
    float* sU  = (float*)sm;               // [128][17]
    float* sDb = (float*)(sm + 12288);     // [16][136]
    const int seg     = (mode == 0) ? (nbase >> 11) : 3;
    const int ncol0   = (mode == 0) ? (nbase & 2047) : nbase;
    const int dbrow   = (mode == 0) ? (seg * 32 + 16) : 112;
    const int ustride = (mode == 0) ? 48 : 16;
    const int uoff    = (mode == 0) ? seg * 16 : 0;

    if (tid < 128) {
        const float* up = Uv + ((size_t)b * 1024 + m0 + tid) * ustride + uoff;
        #pragma unroll
        for (int i = 0; i < 4; i++) {
            float4 v = *(const float4*)(up + i * 4);
            sU[tid * 17 + i * 4 + 0] = v.x;
            sU[tid * 17 + i * 4 + 1] = v.y;
            sU[tid * 17 + i * 4 + 2] = v.z;
            sU[tid * 17 + i * 4 + 3] = v.w;
        }
    }
    #pragma unroll
    for (int i = 0; i < 2; i++) {
        int u = tid + i * 256;
        int r = u >> 5, c4 = (u & 31) * 4;
        float4 v = *(const float4*)(delta + ((size_t)b * 128 + dbrow + r) * 2048 + ncol0 + c4);
        *(float4*)(sDb + r * 136 + c4) = v;
    }
    __syncthreads();

    const int trow = lane >> 2;
    const int tcol = (lane & 3) * 2;
    float* qkvbase = (seg == 0) ? g_q : (seg == 1) ? g_k : g_v;

    #pragma unroll
    for (int mi = 0; mi < 4; mi++) {
        int lr0 = wm * 64 + mi * 16 + trow;
        int lr1 = lr0 + 8;
        #pragma unroll
        for (int r = 0; r < 16; r++) {
            float u0 = sU[lr0 * 17 + r];
            float u1 = sU[lr1 * 17 + r];
            #pragma unroll
            for (int ni = 0; ni < 4; ni++) {
                int c = wn * 32 + ni * 8 + tcol;
                float d0 = sDb[r * 136 + c];
                float d1 = sDb[r * 136 + c + 1];
                acc[mi][ni][0] += u0 * d0;
                acc[mi][ni][1] += u0 * d1;
                acc[mi][ni][2] += u1 * d0;
                acc[mi][ni][3] += u1 * d1;
            }
        }
        #pragma unroll
        for (int ni = 0; ni < 4; ni++) {
            int c = wn * 32 + ni * 8 + tcol;
            if (mode == 0) {
                int h = ncol0 >> 7;
                float* dst = qkvbase + (((size_t)b * 16 + h) * 1024 + m0) * 128;
                *(float2*)(dst + (size_t)lr0 * 128 + c) = make_float2(acc[mi][ni][0], acc[mi][ni][1]);
                *(float2*)(dst + (size_t)lr1 * 128 + c) = make_float2(acc[mi][ni][2], acc[mi][ni][3]);
            } else {
                float* dst = outO + ((size_t)b * 1024 + m0) * 2048 + nbase;
                *(float2*)(dst + (size_t)lr0 * 2048 + c) = make_float2(acc[mi][ni][0], acc[mi][ni][1]);
                *(float2*)(dst + (size_t)lr1 * 2048 + c) = make_float2(acc[mi][ni][2], acc[mi][ni][3]);
            }
        }
    }
}

// ===========================================================================
// RoPE in place on g_q, g_k
// ===========================================================================
__global__ void rope_kernel()
{
    int idx = blockIdx.x * 256 + threadIdx.x;
    if (idx >= BB * HH * TT * 64) return;
    int j  = idx & 63;
    int t  = (idx >> 6) & 1023;
    int bh = idx >> 16;
    float inv = exp2f(-(float)j * (13.2877123795f / 64.0f));
    float ang = (float)t * inv;
    float c, s;
    sincosf(ang, &s, &c);
    size_t base = ((size_t)bh * TT + t) * DD + j;
    float q1 = g_q[base], q2 = g_q[base + 64];
    g_q[base]      = q1 * c - q2 * s;
    g_q[base + 64] = q2 * c + q1 * s;
    float k1 = g_k[base], k2 = g_k[base + 64];
    g_k[base]      = k1 * c - k2 * s;
    g_k[base + 64] = k2 * c + k1 * s;
}

// ===========================================================================
// HMMA flash attention. Grid (T/128, B*H), 256 thr, 8 warps.
// Each warp: 16 q-rows x all keys. S in registers (C-frag -> A-frag identity).
// bf16x3 on QK^T and PV. smem: Q,K,V hi/lo at 272B pitch.
// ===========================================================================
#define AT_PITCH 272
#define AT_QH 0
#define AT_QL 34816
#define AT_KH 69632
#define AT_KL 104448
#define AT_VH 139264
#define AT_VL 174080
#define AT_SMEM 208896

__device__ __forceinline__ void split_pack(float x, float y, uint32_t& hi, uint32_t& lo)
{
    __nv_bfloat16 hx = __float2bfloat16(x), hy = __float2bfloat16(y);
    __nv_bfloat16 lx = __float2bfloat16(x - __bfloat162float(hx));
    __nv_bfloat16 ly = __float2bfloat16(y - __bfloat162float(hy));
    __nv_bfloat162 h; h.x = hx; h.y = hy;
    __nv_bfloat162 l; l.x = lx; l.y = ly;
    hi = *(uint32_t*)&h;
    lo = *(uint32_t*)&l;
}

__global__ __launch_bounds__(256, 1) void attn_h_kernel()
{
    extern __shared__ __align__(16) char sm[];
    const int tid = threadIdx.x, lane = tid & 31, wid = tid >> 5;
    const int qt = blockIdx.x, bh = blockIdx.y;
    const int q0 = qt * 128;
    const size_t tbase = (size_t)bh * 1024;
    const uint32_t sb = smem_u32(sm);

    // Q tiles (hi+lo), loaded once
    #pragma unroll
    for (int i = 0; i < 8; i++) {
        int s = tid + i * 256;
        int row = s >> 4, c = s & 15;
        uint32_t off = (uint32_t)row * AT_PITCH + c * 16;
        size_t g = (tbase + q0 + row) * 128 + c * 8;
        *(uint4*)(sm + AT_QH + off) = *(const uint4*)(g_qhi + g);
        *(uint4*)(sm + AT_QL + off) = *(const uint4*)(g_qlo + g);
    }

    const int gq = lane >> 2, t4 = lane & 3;
    const uint32_t ldRow = (uint32_t)(lane & 15) * AT_PITCH + (lane >> 4) * 16;
    const uint32_t qBase = sb + AT_QH + (uint32_t)(wid * 16) * AT_PITCH + ldRow;

    float o[16][4];
    #pragma unroll
    for (int n = 0; n < 16; n++)
        #pragma unroll
        for (int e = 0; e < 4; e++) o[n][e] = 0.f;
    float mA = -3.0e38f, mB = -3.0e38f, lA = 0.f, lB = 0.f;
    const float scale = 0.08838834764831845f;

    for (int kt = 0; kt < 8; kt++) {
        // K, V tiles for keys [kt*128, kt*128+128)
        #pragma unroll
        for (int i = 0; i < 8; i++) {
            int s = tid + i * 256;
            int row = s >> 4, c = s & 15;
            uint32_t off = (uint32_t)row * AT_PITCH + c * 16;
            size_t g = (tbase + kt * 128 + row) * 128 + c * 8;
            *(uint4*)(sm + AT_KH + off) = *(const uint4*)(g_khi + g);
            *(uint4*)(sm + AT_KL + off) = *(const uint4*)(g_klo + g);
            *(uint4*)(sm + AT_VH + off) = *(const uint4*)(g_vhi + g);
            *(uint4*)(sm + AT_VL + off) = *(const uint4*)(g_vlo + g);
        }
        __syncthreads();

        // ---- S = Q K^T  (16 q-rows x 128 keys per warp) ----
        float s[16][4];
        #pragma unroll
        for (int n = 0; n < 16; n++)
            #pragma unroll
            for (int e = 0; e < 4; e++) s[n][e] = 0.f;

        #pragma unroll
        for (int ks = 0; ks < 8; ks++) {
            uint32_t qh[4], ql[4];
            LDSM_X4(qh, qBase + ks * 32);
            LDSM_X4(ql, qBase + (AT_QL - AT_QH) + ks * 32);
            #pragma unroll
            for (int np = 0; np < 8; np++) {
                uint32_t th[4], tl[4];
                uint32_t ka = sb + AT_KH + ldRow + np * (16 * AT_PITCH) + ks * 32;
                LDSM_X4(th, ka);
                LDSM_X4(tl, ka + (AT_KL - AT_KH));
                uint32_t b0h[2] = {th[0], th[2]}, b1h[2] = {th[1], th[3]};
                uint32_t b0l[2] = {tl[0], tl[2]}, b1l[2] = {tl[1], tl[3]};
                MMA_BF16(s[2 * np],     qh, b0h);
                MMA_BF16(s[2 * np],     ql, b0h);
                MMA_BF16(s[2 * np],     qh, b0l);
                MMA_BF16(s[2 * np + 1], qh, b1h);
                MMA_BF16(s[2 * np + 1], ql, b1h);
                MMA_BF16(s[2 * np + 1], qh, b1l);
            }
        }

        // ---- online softmax on register fragments ----
        float mxA = -3.0e38f, mxB = -3.0e38f;
        #pragma unroll
        for (int n = 0; n < 16; n++) {
            mxA = fmaxf(mxA, fmaxf(s[n][0], s[n][1]));
            mxB = fmaxf(mxB, fmaxf(s[n][2], s[n][3]));
        }
        mxA = fmaxf(mxA, __shfl_xor_sync(0xffffffffu, mxA, 1));
        mxA = fmaxf(mxA, __shfl_xor_sync(0xffffffffu, mxA, 2));
        mxB = fmaxf(mxB, __shfl_xor_sync(0xffffffffu, mxB, 1));
        mxB = fmaxf(mxB, __shfl_xor_sync(0xffffffffu, mxB, 2));
        float nmA = fmaxf(mA, mxA * scale);
        float nmB = fmaxf(mB, mxB * scale);
        float aA = __expf(mA - nmA), aB = __expf(mB - nmB);
        mA = nmA; mB = nmB;
        float sumA = 0.f, sumB = 0.f;
        #pragma unroll
        for (int n = 0; n < 16; n++) {
            s[n][0] = __expf(s[n][0] * scale - mA); sumA += s[n][0];
            s[n][1] = __expf(s[n][1] * scale - mA); sumA += s[n][1];
            s[n][2] = __expf(s[n][2] * scale - mB); sumB += s[n][2];
            s[n][3] = __expf(s[n][3] * scale - mB); sumB += s[n][3];
        }
        sumA += __shfl_xor_sync(0xffffffffu, sumA, 1);
        sumA += __shfl_xor_sync(0xffffffffu, sumA, 2);
        sumB += __shfl_xor_sync(0xffffffffu, sumB, 1);
        sumB += __shfl_xor_sync(0xffffffffu, sumB, 2);
        lA = lA * aA + sumA;
        lB = lB * aB + sumB;
        #pragma unroll
        for (int n = 0; n < 16; n++) {
            o[n][0] *= aA; o[n][1] *= aA;
            o[n][2] *= aB; o[n][3] *= aB;
        }

        // ---- O += P V ----
        #pragma unroll
        for (int kk = 0; kk < 8; kk++) {
            uint32_t ah[4], al[4];
            split_pack(s[2 * kk][0],     s[2 * kk][1],     ah[0], al[0]);
            split_pack(s[2 * kk][2],     s[2 * kk][3],     ah[1], al[1]);
            split_pack(s[2 * kk + 1][0], s[2 * kk + 1][1], ah[2], al[2]);
            split_pack(s[2 * kk + 1][2], s[2 * kk + 1][3], ah[3], al[3]);
            #pragma unroll
            for (int np = 0; np < 8; np++) {
                uint32_t tv[4], tw[4];
                uint32_t va = sb + AT_VH + ldRow + kk * (16 * AT_PITCH) + np * 32;
                LDSM_X4_T(tv, va);
                LDSM_X4_T(tw, va + (AT_VL - AT_VH));
                uint32_t b0h[2] = {tv[0], tv[1]}, b1h[2] = {tv[2], tv[3]};
                uint32_t b0l[2] = {tw[0], tw[1]}, b1l[2] = {tw[2], tw[3]};
                MMA_BF16(o[2 * np],     ah, b0h);
                MMA_BF16(o[2 * np],     al, b0h);
                MMA_BF16(o[2 * np],     ah, b0l);
                MMA_BF16(o[2 * np + 1], ah, b1h);
                MMA_BF16(o[2 * np + 1], al, b1h);
                MMA_BF16(o[2 * np + 1], ah, b1l);
            }
        }
        __syncthreads();
    }

    // ---- normalize + write to g_y (B,T,C), head h cols ----
    int b = bh >> 4, h = bh & 15;
    float iA = 1.f / lA, iB = 1.f / lB;
    int rA = q0 + wid * 16 + gq, rB = rA + 8;
    float* ybA = g_y + ((size_t)b * TT + rA) * CC + h * 128;
    float* ybB = g_y + ((size_t)b * TT + rB) * CC + h * 128;
    #pragma unroll
    for (int n = 0; n < 16; n++) {
        int d = n * 8 + t4 * 2;
        *(float2*)(ybA + d) = make_float2(o[n][0] * iA, o[n][1] * iA);
        *(float2*)(ybB + d) = make_float2(o[n][2] * iB, o[n][3] * iB);
    }
}

// ===========================================================================
extern "C" void kernel_launch(void* const* d_in, const int* in_sizes, int n_in,
                              void* d_out, int out_size)
{
    const float* x     = (const float*)d_in[0];
    const float* delta = (const float*)d_in[1];
    const float* Wq    = (const float*)d_in[2];
    const float* Wk    = (const float*)d_in[3];
    const float* Wv    = (const float*)d_in[4];
    const float* Wo    = (const float*)d_in[5];
    float* out = (float*)d_out;

    cudaFuncSetAttribute(mmh_kernel, cudaFuncAttributeMaxDynamicSharedMemorySize,
                         MMH_SMEM);
    cudaFuncSetAttribute(attn_h_kernel, cudaFuncAttributeMaxDynamicSharedMemorySize,
                         AT_SMEM);

    split_w_kernel<<<dim3(4096, 4), 256>>>(Wq, Wk, Wv, Wo);
    split_xy_kernel<<<8192, 256>>>(x, 0);
    lora_u_kernel<<<BB * TT, 256>>>(x, delta, 0);
    mmh_kernel<<<dim3(48, 8, BB), 256, MMH_SMEM>>>(delta, 0, nullptr);
    rope_kernel<<<(BB * HH * TT * 64) / 256, 256>>>();
    split_qkv_kernel<<<dim3(8192, 3), 256>>>();
    attn_h_kernel<<<dim3(8, BB * HH), 256, AT_SMEM>>>();
    lora_u_kernel<<<BB * TT, 256>>>(x, delta, 1);
    split_xy_kernel<<<8192, 256>>>(x, 1);
    mmh_kernel<<<dim3(16, 8, BB), 256, MMH_SMEM>>>(delta, 1, out);
}

// round 11
// speedup vs baseline: 2.3214x; 1.0095x over previous
#include <cuda_runtime.h>
#include <cuda_bf16.h>
#include <stdint.h>
#include <math.h>

#define BB 4
#define TT 1024
#define CC 2048
#define HH 16
#define DD 128

typedef unsigned long long u64;

__device__ __forceinline__ uint32_t smem_u32(const void* p) {
    uint32_t a;
    asm("{ .reg .u64 t; cvta.to.shared.u64 t, %1; cvt.u32.u64 %0, t; }" : "=r"(a) : "l"(p));
    return a;
}

// ===========================================================================
// HMMA path: ldmatrix + mma.sync + cp.async (sm_80 baseline ISA)
// ===========================================================================
#define LDSM_X4(r, addr) \
    asm volatile("ldmatrix.sync.aligned.m8n8.x4.shared.b16 {%0,%1,%2,%3}, [%4];" \
        : "=r"((r)[0]), "=r"((r)[1]), "=r"((r)[2]), "=r"((r)[3]) : "r"(addr))

#define LDSM_X4_T(r, addr) \
    asm volatile("ldmatrix.sync.aligned.m8n8.x4.trans.shared.b16 {%0,%1,%2,%3}, [%4];" \
        : "=r"((r)[0]), "=r"((r)[1]), "=r"((r)[2]), "=r"((r)[3]) : "r"(addr))

#define MMA_BF16(d, a, b) \
    asm volatile("mma.sync.aligned.m16n8k16.row.col.f32.bf16.bf16.f32 " \
        "{%0,%1,%2,%3}, {%4,%5,%6,%7}, {%8,%9}, {%0,%1,%2,%3};" \
        : "+f"((d)[0]), "+f"((d)[1]), "+f"((d)[2]), "+f"((d)[3]) \
        : "r"((a)[0]), "r"((a)[1]), "r"((a)[2]), "r"((a)[3]), \
          "r"((b)[0]), "r"((b)[1]))

#define CP_ASYNC16(saddr, gptr) \
    asm volatile("cp.async.cg.shared.global [%0], [%1], 16;" \
        :: "r"(saddr), "l"(gptr) : "memory")
#define CP_COMMIT() asm volatile("cp.async.commit_group;" ::: "memory")
#define CP_WAIT1()  asm volatile("cp.async.wait_group 1;" ::: "memory")
#define CP_WAIT0()  asm volatile("cp.async.wait_group 0;" ::: "memory")

// ===========================================================================
// Scratch (device globals — no allocation allowed)
// ===========================================================================
__device__ float g_q[8388608];   // (B,H,T,D)
__device__ float g_k[8388608];
__device__ float g_v[8388608];
__device__ float g_y[8388608];   // (B,T,C)
__device__ float g_u[196608];    // (B,T,48)
__device__ float g_uo[65536];    // (B,T,16)
__device__ __align__(16) __nv_bfloat16 g_xhi[8388608];
__device__ __align__(16) __nv_bfloat16 g_xlo[8388608];
__device__ __align__(16) __nv_bfloat16 g_yhi[8388608];
__device__ __align__(16) __nv_bfloat16 g_ylo[8388608];
__device__ __align__(16) __nv_bfloat16 g_whi[16777216];  // [q|k|v|o][2048][2048]
__device__ __align__(16) __nv_bfloat16 g_wlo[16777216];
__device__ __align__(16) __nv_bfloat16 g_qhi[8388608];
__device__ __align__(16) __nv_bfloat16 g_qlo[8388608];
__device__ __align__(16) __nv_bfloat16 g_khi[8388608];
__device__ __align__(16) __nv_bfloat16 g_klo[8388608];
__device__ __align__(16) __nv_bfloat16 g_vhi[8388608];
__device__ __align__(16) __nv_bfloat16 g_vlo[8388608];

// ===========================================================================
// fp32 -> bf16 hi/lo split kernels
// ===========================================================================
__device__ __forceinline__ void split4(float4 v, __nv_bfloat16* hi, __nv_bfloat16* lo) {
    __nv_bfloat16 h0 = __float2bfloat16(v.x), h1 = __float2bfloat16(v.y);
    __nv_bfloat16 h2 = __float2bfloat16(v.z), h3 = __float2bfloat16(v.w);
    __nv_bfloat16 l0 = __float2bfloat16(v.x - __bfloat162float(h0));
    __nv_bfloat16 l1 = __float2bfloat16(v.y - __bfloat162float(h1));
    __nv_bfloat16 l2 = __float2bfloat16(v.z - __bfloat162float(h2));
    __nv_bfloat16 l3 = __float2bfloat16(v.w - __bfloat162float(h3));
    __nv_bfloat162 p;
    p.x = h0; p.y = h1; *(__nv_bfloat162*)(hi)     = p;
    p.x = h2; p.y = h3; *(__nv_bfloat162*)(hi + 2) = p;
    p.x = l0; p.y = l1; *(__nv_bfloat162*)(lo)     = p;
    p.x = l2; p.y = l3; *(__nv_bfloat162*)(lo + 2) = p;
}

__global__ void split_xy_kernel(const float* __restrict__ x, int mode)
{
    int i = (blockIdx.x * 256 + threadIdx.x) * 4;
    const float* src = (mode == 0) ? x : (const float*)g_y;
    __nv_bfloat16* hi = (mode == 0) ? g_xhi : g_yhi;
    __nv_bfloat16* lo = (mode == 0) ? g_xlo : g_ylo;
    split4(*(const float4*)(src + i), hi + i, lo + i);
}

__global__ void split_w_kernel(const float* __restrict__ Wq, const float* __restrict__ Wk,
                               const float* __restrict__ Wv, const float* __restrict__ Wo)
{
    int j = blockIdx.y;
    const float* src = (j == 0) ? Wq : (j == 1) ? Wk : (j == 2) ? Wv : Wo;
    size_t base = (size_t)j * 4194304;
    int i = (blockIdx.x * 256 + threadIdx.x) * 4;
    split4(*(const float4*)(src + i), g_whi + base + i, g_wlo + base + i);
}

__global__ void split_qkv_kernel()
{
    int j = blockIdx.y;
    const float* src = (j == 0) ? g_q : (j == 1) ? g_k : g_v;
    __nv_bfloat16* hi = (j == 0) ? g_qhi : (j == 1) ? g_khi : g_vhi;
    __nv_bfloat16* lo = (j == 0) ? g_qlo : (j == 1) ? g_klo : g_vlo;
    int i = (blockIdx.x * 256 + threadIdx.x) * 4;
    split4(*(const float4*)(src + i), hi + i, lo + i);
}

// ===========================================================================
// LoRA left factor. mode 0: U = x @ dA^T (48 cols), mode 1: Uo = y @ doA^T
// ===========================================================================
__global__ void lora_u_kernel(const float* __restrict__ x,
                              const float* __restrict__ delta, int mode)
{
    int bt = blockIdx.x;
    int b  = bt >> 10;
    const float* src  = (mode == 0) ? x : (const float*)g_y;
    const float* xrow = src + (size_t)bt * CC;
    float* dst = (mode == 0) ? g_u : g_uo;
    int nOut   = (mode == 0) ? 48 : 16;

    int lane = threadIdx.x & 31, w = threadIdx.x >> 5;
    for (int j = w; j < nOut; j += 8) {
        int row = (mode == 0) ? ((j >> 4) * 32 + (j & 15)) : (96 + j);
        const float* arow = delta + ((size_t)b * 128 + row) * CC;
        float s = 0.f;
        for (int i = lane * 4; i < CC; i += 128) {
            float4 xv = *(const float4*)(xrow + i);
            float4 av = *(const float4*)(arow + i);
            s += xv.x * av.x + xv.y * av.y + xv.z * av.z + xv.w * av.w;
        }
        #pragma unroll
        for (int o = 16; o; o >>= 1) s += __shfl_xor_sync(0xffffffffu, s, o);
        if (lane == 0) dst[(size_t)bt * nOut + j] = s;
    }
}

// ===========================================================================
// bf16x3 GEMM on mma.sync + cp.async 3-stage pipeline.
// Tile 128(M) x 128(N), K-stage 32, 8 warps (2m x 4n), warp tile 64x32.
// Smem rows padded to 80B. 3 stages x 40KB.
// mode 0: QKV from g_xhi/g_xlo, head-layout out. mode 1: O from g_yhi/g_ylo.
// ===========================================================================
#define MMH_STAGE 40960
#define MMH_SMEM  (3 * MMH_STAGE)

__global__ __launch_bounds__(256, 1)
void mmh_kernel(const float* __restrict__ delta, int mode, float* __restrict__ outO)
{
    extern __shared__ __align__(16) char sm[];
    const int tid = threadIdx.x, lane = tid & 31, wid = tid >> 5;
    const int wm = wid >> 2, wn = wid & 3;
    const int b = blockIdx.z, mt = blockIdx.y, nt = blockIdx.x;
    const int m0 = mt * 128, nbase = nt * 128;
    const int wrow0 = (mode == 0) ? nbase : (6144 + nbase);
    const size_t arow0 = (size_t)b * 1024 + m0;

    const __nv_bfloat16* Ahi = (mode == 0) ? g_xhi : g_yhi;
    const __nv_bfloat16* Alo = (mode == 0) ? g_xlo : g_ylo;
    const float* Uv = (mode == 0) ? g_u : g_uo;

    const int r0 = tid >> 2, s0 = tid & 3;
    const int r1 = r0 + 64;
    const __nv_bfloat16* gAh0 = Ahi + (arow0 + r0) * 2048 + s0 * 8;
    const __nv_bfloat16* gAh1 = Ahi + (arow0 + r1) * 2048 + s0 * 8;
    const __nv_bfloat16* gAl0 = Alo + (arow0 + r0) * 2048 + s0 * 8;
    const __nv_bfloat16* gAl1 = Alo + (arow0 + r1) * 2048 + s0 * 8;
    const __nv_bfloat16* gBh0 = g_whi + (size_t)(wrow0 + r0) * 2048 + s0 * 8;
    const __nv_bfloat16* gBh1 = g_whi + (size_t)(wrow0 + r1) * 2048 + s0 * 8;
    const __nv_bfloat16* gBl0 = g_wlo + (size_t)(wrow0 + r0) * 2048 + s0 * 8;
    const __nv_bfloat16* gBl1 = g_wlo + (size_t)(wrow0 + r1) * 2048 + s0 * 8;
    const uint32_t so0 = (uint32_t)r0 * 80 + s0 * 16;
    const uint32_t so1 = (uint32_t)r1 * 80 + s0 * 16;
    const uint32_t sb = smem_u32(sm);

    float acc[4][4][4];
    #pragma unroll
    for (int mi = 0; mi < 4; mi++)
        #pragma unroll
        for (int ni = 0; ni < 4; ni++)
            #pragma unroll
            for (int e = 0; e < 4; e++) acc[mi][ni][e] = 0.f;

    // issue all 8 16B cp.asyncs for stage buffer sbase, K-chunk kt
    #define MMH_ISSUE(sbase, kt) do { \
        int kk = (kt) * 32; \
        CP_ASYNC16((sbase) + so0,         gAh0 + kk); \
        CP_ASYNC16((sbase) + so1,         gAh1 + kk); \
        CP_ASYNC16((sbase) + 10240 + so0, gAl0 + kk); \
        CP_ASYNC16((sbase) + 10240 + so1, gAl1 + kk); \
        CP_ASYNC16((sbase) + 20480 + so0, gBh0 + kk); \
        CP_ASYNC16((sbase) + 20480 + so1, gBh1 + kk); \
        CP_ASYNC16((sbase) + 30720 + so0, gBl0 + kk); \
        CP_ASYNC16((sbase) + 30720 + so1, gBl1 + kk); \
    } while (0)

    MMH_ISSUE(sb, 0);              CP_COMMIT();
    MMH_ISSUE(sb + MMH_STAGE, 1);  CP_COMMIT();

    const uint32_t aRowBase = (uint32_t)(wm * 64 + (lane & 15)) * 80 + (lane >> 4) * 16;
    const uint32_t bRowBase = (uint32_t)(wn * 32 + (lane & 15)) * 80 + (lane >> 4) * 16;

    int buf = 0, nxt = 2;   // buf = stage of kt, nxt = stage index for kt+2
    for (int kt = 0; kt < 64; kt++) {
        CP_WAIT1();
        __syncthreads();
        if (kt < 62) MMH_ISSUE(sb + nxt * MMH_STAGE, kt + 2);
        CP_COMMIT();   // uniform group count (empty groups at tail)

        uint32_t sA = sb + buf * MMH_STAGE;
        uint32_t sB = sA + 20480;
        #pragma unroll
        for (int ks = 0; ks < 2; ks++) {
            uint32_t ah[4][4], al[4][4], bh[4][2], bl[4][2];
            #pragma unroll
            for (int mi = 0; mi < 4; mi++) {
                uint32_t ad = sA + aRowBase + mi * (16 * 80) + ks * 32;
                LDSM_X4(ah[mi], ad);
                LDSM_X4(al[mi], ad + 10240);
            }
            #pragma unroll
            for (int g = 0; g < 2; g++) {
                uint32_t bd = sB + bRowBase + g * (16 * 80) + ks * 32;
                uint32_t t[4], tl[4];
                LDSM_X4(t, bd);
                LDSM_X4(tl, bd + 10240);
                bh[g * 2][0] = t[0];  bh[g * 2][1] = t[2];
                bh[g * 2 + 1][0] = t[1]; bh[g * 2 + 1][1] = t[3];
                bl[g * 2][0] = tl[0]; bl[g * 2][1] = tl[2];
                bl[g * 2 + 1][0] = tl[1]; bl[g * 2 + 1][1] = tl[3];
            }
            #pragma unroll
            for (int mi = 0; mi < 4; mi++)
                #pragma unroll
                for (int ni = 0; ni < 4; ni++) {
                    MMA_BF16(acc[mi][ni], ah[mi], bh[ni]);
                    MMA_BF16(acc[mi][ni], al[mi], bh[ni]);
                    MMA_BF16(acc[mi][ni], ah[mi], bl[ni]);
                }
        }
        buf = (buf == 2) ? 0 : buf + 1;
        nxt = (nxt == 2) ? 0 : nxt + 1;
    }
    CP_WAIT0();
    __syncthreads();

    // ---- LoRA epilogue + writeback ----
    float* sU  = (float*)sm;               // [128][17]
    float* sDb = (float*)(sm + 12288);     // [16][136]
    const int seg     = (mode == 0) ? (nbase >> 11) : 3;
    const int ncol0   = (mode == 0) ? (nbase & 2047) : nbase;
    const int dbrow   = (mode == 0) ? (seg * 32 + 16) : 112;
    const int ustride = (mode == 0) ? 48 : 16;
    const int uoff    = (mode == 0) ? seg * 16 : 0;

    if (tid < 128) {
        const float* up = Uv + ((size_t)b * 1024 + m0 + tid) * ustride + uoff;
        #pragma unroll
        for (int i = 0; i < 4; i++) {
            float4 v = *(const float4*)(up + i * 4);
            sU[tid * 17 + i * 4 + 0] = v.x;
            sU[tid * 17 + i * 4 + 1] = v.y;
            sU[tid * 17 + i * 4 + 2] = v.z;
            sU[tid * 17 + i * 4 + 3] = v.w;
        }
    }
    #pragma unroll
    for (int i = 0; i < 2; i++) {
        int u = tid + i * 256;
        int r = u >> 5, c4 = (u & 31) * 4;
        float4 v = *(const float4*)(delta + ((size_t)b * 128 + dbrow + r) * 2048 + ncol0 + c4);
        *(float4*)(sDb + r * 136 + c4) = v;
    }
    __syncthreads();

    const int trow = lane >> 2;
    const int tcol = (lane & 3) * 2;
    float* qkvbase = (seg == 0) ? g_q : (seg == 1) ? g_k : g_v;

    #pragma unroll
    for (int mi = 0; mi < 4; mi++) {
        int lr0 = wm * 64 + mi * 16 + trow;
        int lr1 = lr0 + 8;
        #pragma unroll
        for (int r = 0; r < 16; r++) {
            float u0 = sU[lr0 * 17 + r];
            float u1 = sU[lr1 * 17 + r];
            #pragma unroll
            for (int ni = 0; ni < 4; ni++) {
                int c = wn * 32 + ni * 8 + tcol;
                float d0 = sDb[r * 136 + c];
                float d1 = sDb[r * 136 + c + 1];
                acc[mi][ni][0] += u0 * d0;
                acc[mi][ni][1] += u0 * d1;
                acc[mi][ni][2] += u1 * d0;
                acc[mi][ni][3] += u1 * d1;
            }
        }
        #pragma unroll
        for (int ni = 0; ni < 4; ni++) {
            int c = wn * 32 + ni * 8 + tcol;
            if (mode == 0) {
                int h = ncol0 >> 7;
                float* dst = qkvbase + (((size_t)b * 16 + h) * 1024 + m0) * 128;
                *(float2*)(dst + (size_t)lr0 * 128 + c) = make_float2(acc[mi][ni][0], acc[mi][ni][1]);
                *(float2*)(dst + (size_t)lr1 * 128 + c) = make_float2(acc[mi][ni][2], acc[mi][ni][3]);
            } else {
                float* dst = outO + ((size_t)b * 1024 + m0) * 2048 + nbase;
                *(float2*)(dst + (size_t)lr0 * 2048 + c) = make_float2(acc[mi][ni][0], acc[mi][ni][1]);
                *(float2*)(dst + (size_t)lr1 * 2048 + c) = make_float2(acc[mi][ni][2], acc[mi][ni][3]);
            }
        }
    }
}

// ===========================================================================
// RoPE in place on g_q, g_k
// ===========================================================================
__global__ void rope_kernel()
{
    int idx = blockIdx.x * 256 + threadIdx.x;
    if (idx >= BB * HH * TT * 64) return;
    int j  = idx & 63;
    int t  = (idx >> 6) & 1023;
    int bh = idx >> 16;
    float inv = exp2f(-(float)j * (13.2877123795f / 64.0f));
    float ang = (float)t * inv;
    float c, s;
    sincosf(ang, &s, &c);
    size_t base = ((size_t)bh * TT + t) * DD + j;
    float q1 = g_q[base], q2 = g_q[base + 64];
    g_q[base]      = q1 * c - q2 * s;
    g_q[base + 64] = q2 * c + q1 * s;
    float k1 = g_k[base], k2 = g_k[base + 64];
    g_k[base]      = k1 * c - k2 * s;
    g_k[base + 64] = k2 * c + k1 * s;
}

// ===========================================================================
// HMMA flash attention (round-10 passing version, unchanged)
// ===========================================================================
#define AT_PITCH 272
#define AT_QH 0
#define AT_QL 34816
#define AT_KH 69632
#define AT_KL 104448
#define AT_VH 139264
#define AT_VL 174080
#define AT_SMEM 208896

__device__ __forceinline__ void split_pack(float x, float y, uint32_t& hi, uint32_t& lo)
{
    __nv_bfloat16 hx = __float2bfloat16(x), hy = __float2bfloat16(y);
    __nv_bfloat16 lx = __float2bfloat16(x - __bfloat162float(hx));
    __nv_bfloat16 ly = __float2bfloat16(y - __bfloat162float(hy));
    __nv_bfloat162 h; h.x = hx; h.y = hy;
    __nv_bfloat162 l; l.x = lx; l.y = ly;
    hi = *(uint32_t*)&h;
    lo = *(uint32_t*)&l;
}

__global__ __launch_bounds__(256, 1) void attn_h_kernel()
{
    extern __shared__ __align__(16) char sm[];
    const int tid = threadIdx.x, lane = tid & 31, wid = tid >> 5;
    const int qt = blockIdx.x, bh = blockIdx.y;
    const int q0 = qt * 128;
    const size_t tbase = (size_t)bh * 1024;
    const uint32_t sb = smem_u32(sm);

    #pragma unroll
    for (int i = 0; i < 8; i++) {
        int s = tid + i * 256;
        int row = s >> 4, c = s & 15;
        uint32_t off = (uint32_t)row * AT_PITCH + c * 16;
        size_t g = (tbase + q0 + row) * 128 + c * 8;
        *(uint4*)(sm + AT_QH + off) = *(const uint4*)(g_qhi + g);
        *(uint4*)(sm + AT_QL + off) = *(const uint4*)(g_qlo + g);
    }

    const int gq = lane >> 2, t4 = lane & 3;
    const uint32_t ldRow = (uint32_t)(lane & 15) * AT_PITCH + (lane >> 4) * 16;
    const uint32_t qBase = sb + AT_QH + (uint32_t)(wid * 16) * AT_PITCH + ldRow;

    float o[16][4];
    #pragma unroll
    for (int n = 0; n < 16; n++)
        #pragma unroll
        for (int e = 0; e < 4; e++) o[n][e] = 0.f;
    float mA = -3.0e38f, mB = -3.0e38f, lA = 0.f, lB = 0.f;
    const float scale = 0.08838834764831845f;

    for (int kt = 0; kt < 8; kt++) {
        #pragma unroll
        for (int i = 0; i < 8; i++) {
            int s = tid + i * 256;
            int row = s >> 4, c = s & 15;
            uint32_t off = (uint32_t)row * AT_PITCH + c * 16;
            size_t g = (tbase + kt * 128 + row) * 128 + c * 8;
            *(uint4*)(sm + AT_KH + off) = *(const uint4*)(g_khi + g);
            *(uint4*)(sm + AT_KL + off) = *(const uint4*)(g_klo + g);
            *(uint4*)(sm + AT_VH + off) = *(const uint4*)(g_vhi + g);
            *(uint4*)(sm + AT_VL + off) = *(const uint4*)(g_vlo + g);
        }
        __syncthreads();

        float s[16][4];
        #pragma unroll
        for (int n = 0; n < 16; n++)
            #pragma unroll
            for (int e = 0; e < 4; e++) s[n][e] = 0.f;

        #pragma unroll
        for (int ks = 0; ks < 8; ks++) {
            uint32_t qh[4], ql[4];
            LDSM_X4(qh, qBase + ks * 32);
            LDSM_X4(ql, qBase + (AT_QL - AT_QH) + ks * 32);
            #pragma unroll
            for (int np = 0; np < 8; np++) {
                uint32_t th[4], tl[4];
                uint32_t ka = sb + AT_KH + ldRow + np * (16 * AT_PITCH) + ks * 32;
                LDSM_X4(th, ka);
                LDSM_X4(tl, ka + (AT_KL - AT_KH));
                uint32_t b0h[2] = {th[0], th[2]}, b1h[2] = {th[1], th[3]};
                uint32_t b0l[2] = {tl[0], tl[2]}, b1l[2] = {tl[1], tl[3]};
                MMA_BF16(s[2 * np],     qh, b0h);
                MMA_BF16(s[2 * np],     ql, b0h);
                MMA_BF16(s[2 * np],     qh, b0l);
                MMA_BF16(s[2 * np + 1], qh, b1h);
                MMA_BF16(s[2 * np + 1], ql, b1h);
                MMA_BF16(s[2 * np + 1], qh, b1l);
            }
        }

        float mxA = -3.0e38f, mxB = -3.0e38f;
        #pragma unroll
        for (int n = 0; n < 16; n++) {
            mxA = fmaxf(mxA, fmaxf(s[n][0], s[n][1]));
            mxB = fmaxf(mxB, fmaxf(s[n][2], s[n][3]));
        }
        mxA = fmaxf(mxA, __shfl_xor_sync(0xffffffffu, mxA, 1));
        mxA = fmaxf(mxA, __shfl_xor_sync(0xffffffffu, mxA, 2));
        mxB = fmaxf(mxB, __shfl_xor_sync(0xffffffffu, mxB, 1));
        mxB = fmaxf(mxB, __shfl_xor_sync(0xffffffffu, mxB, 2));
        float nmA = fmaxf(mA, mxA * scale);
        float nmB = fmaxf(mB, mxB * scale);
        float aA = __expf(mA - nmA), aB = __expf(mB - nmB);
        mA = nmA; mB = nmB;
        float sumA = 0.f, sumB = 0.f;
        #pragma unroll
        for (int n = 0; n < 16; n++) {
            s[n][0] = __expf(s[n][0] * scale - mA); sumA += s[n][0];
            s[n][1] = __expf(s[n][1] * scale - mA); sumA += s[n][1];
            s[n][2] = __expf(s[n][2] * scale - mB); sumB += s[n][2];
            s[n][3] = __expf(s[n][3] * scale - mB); sumB += s[n][3];
        }
        sumA += __shfl_xor_sync(0xffffffffu, sumA, 1);
        sumA += __shfl_xor_sync(0xffffffffu, sumA, 2);
        sumB += __shfl_xor_sync(0xffffffffu, sumB, 1);
        sumB += __shfl_xor_sync(0xffffffffu, sumB, 2);
        lA = lA * aA + sumA;
        lB = lB * aB + sumB;
        #pragma unroll
        for (int n = 0; n < 16; n++) {
            o[n][0] *= aA; o[n][1] *= aA;
            o[n][2] *= aB; o[n][3] *= aB;
        }

        #pragma unroll
        for (int kk = 0; kk < 8; kk++) {
            uint32_t ah[4], al[4];
            split_pack(s[2 * kk][0],     s[2 * kk][1],     ah[0], al[0]);
            split_pack(s[2 * kk][2],     s[2 * kk][3],     ah[1], al[1]);
            split_pack(s[2 * kk + 1][0], s[2 * kk + 1][1], ah[2], al[2]);
            split_pack(s[2 * kk + 1][2], s[2 * kk + 1][3], ah[3], al[3]);
            #pragma unroll
            for (int np = 0; np < 8; np++) {
                uint32_t tv[4], tw[4];
                uint32_t va = sb + AT_VH + ldRow + kk * (16 * AT_PITCH) + np * 32;
                LDSM_X4_T(tv, va);
                LDSM_X4_T(tw, va + (AT_VL - AT_VH));
                uint32_t b0h[2] = {tv[0], tv[1]}, b1h[2] = {tv[2], tv[3]};
                uint32_t b0l[2] = {tw[0], tw[1]}, b1l[2] = {tw[2], tw[3]};
                MMA_BF16(o[2 * np],     ah, b0h);
                MMA_BF16(o[2 * np],     al, b0h);
                MMA_BF16(o[2 * np],     ah, b0l);
                MMA_BF16(o[2 * np + 1], ah, b1h);
                MMA_BF16(o[2 * np + 1], al, b1h);
                MMA_BF16(o[2 * np + 1], ah, b1l);
            }
        }
        __syncthreads();
    }

    int b = bh >> 4, h = bh & 15;
    float iA = 1.f / lA, iB = 1.f / lB;
    int rA = q0 + wid * 16 + gq, rB = rA + 8;
    float* ybA = g_y + ((size_t)b * TT + rA) * CC + h * 128;
    float* ybB = g_y + ((size_t)b * TT + rB) * CC + h * 128;
    #pragma unroll
    for (int n = 0; n < 16; n++) {
        int d = n * 8 + t4 * 2;
        *(float2*)(ybA + d) = make_float2(o[n][0] * iA, o[n][1] * iA);
        *(float2*)(ybB + d) = make_float2(o[n][2] * iB, o[n][3] * iB);
    }
}

// ===========================================================================
extern "C" void kernel_launch(void* const* d_in, const int* in_sizes, int n_in,
                              void* d_out, int out_size)
{
    const float* x     = (const float*)d_in[0];
    const float* delta = (const float*)d_in[1];
    const float* Wq    = (const float*)d_in[2];
    const float* Wk    = (const float*)d_in[3];
    const float* Wv    = (const float*)d_in[4];
    const float* Wo    = (const float*)d_in[5];
    float* out = (float*)d_out;

    cudaFuncSetAttribute(mmh_kernel, cudaFuncAttributeMaxDynamicSharedMemorySize,
                         MMH_SMEM);
    cudaFuncSetAttribute(attn_h_kernel, cudaFuncAttributeMaxDynamicSharedMemorySize,
                         AT_SMEM);

    split_w_kernel<<<dim3(4096, 4), 256>>>(Wq, Wk, Wv, Wo);
    split_xy_kernel<<<8192, 256>>>(x, 0);
    lora_u_kernel<<<BB * TT, 256>>>(x, delta, 0);
    mmh_kernel<<<dim3(48, 8, BB), 256, MMH_SMEM>>>(delta, 0, nullptr);
    rope_kernel<<<(BB * HH * TT * 64) / 256, 256>>>();
    split_qkv_kernel<<<dim3(8192, 3), 256>>>();
    attn_h_kernel<<<dim3(8, BB * HH), 256, AT_SMEM>>>();
    lora_u_kernel<<<BB * TT, 256>>>(x, delta, 1);
    split_xy_kernel<<<8192, 256>>>(x, 1);
    mmh_kernel<<<dim3(16, 8, BB), 256, MMH_SMEM>>>(delta, 1, out);
}

// round 12
// speedup vs baseline: 2.3603x; 1.0167x over previous
#include <cuda_runtime.h>
#include <cuda_bf16.h>
#include <stdint.h>
#include <math.h>

#define BB 4
#define TT 1024
#define CC 2048
#define HH 16
#define DD 128

typedef unsigned long long u64;

__device__ __forceinline__ uint32_t smem_u32(const void* p) {
    uint32_t a;
    asm("{ .reg .u64 t; cvta.to.shared.u64 t, %1; cvt.u32.u64 %0, t; }" : "=r"(a) : "l"(p));
    return a;
}

// ===========================================================================
// HMMA path: ldmatrix + mma.sync + cp.async (sm_80 baseline ISA)
// ===========================================================================
#define LDSM_X4(r, addr) \
    asm volatile("ldmatrix.sync.aligned.m8n8.x4.shared.b16 {%0,%1,%2,%3}, [%4];" \
        : "=r"((r)[0]), "=r"((r)[1]), "=r"((r)[2]), "=r"((r)[3]) : "r"(addr))

#define LDSM_X4_T(r, addr) \
    asm volatile("ldmatrix.sync.aligned.m8n8.x4.trans.shared.b16 {%0,%1,%2,%3}, [%4];" \
        : "=r"((r)[0]), "=r"((r)[1]), "=r"((r)[2]), "=r"((r)[3]) : "r"(addr))

#define MMA_BF16(d, a, b) \
    asm volatile("mma.sync.aligned.m16n8k16.row.col.f32.bf16.bf16.f32 " \
        "{%0,%1,%2,%3}, {%4,%5,%6,%7}, {%8,%9}, {%0,%1,%2,%3};" \
        : "+f"((d)[0]), "+f"((d)[1]), "+f"((d)[2]), "+f"((d)[3]) \
        : "r"((a)[0]), "r"((a)[1]), "r"((a)[2]), "r"((a)[3]), \
          "r"((b)[0]), "r"((b)[1]))

#define CP_ASYNC16(saddr, gptr) \
    asm volatile("cp.async.cg.shared.global [%0], [%1], 16;" \
        :: "r"(saddr), "l"(gptr) : "memory")
#define CP_COMMIT() asm volatile("cp.async.commit_group;" ::: "memory")
#define CP_WAIT1()  asm volatile("cp.async.wait_group 1;" ::: "memory")
#define CP_WAIT0()  asm volatile("cp.async.wait_group 0;" ::: "memory")

// ===========================================================================
// Scratch (device globals — no allocation allowed)
// ===========================================================================
__device__ float g_q[8388608];   // (B,H,T,D)
__device__ float g_k[8388608];
__device__ float g_v[8388608];
__device__ float g_y[8388608];   // (B,T,C)
__device__ float g_u[196608];    // (B,T,48)
__device__ float g_uo[65536];    // (B,T,16)
__device__ __align__(16) __nv_bfloat16 g_xhi[8388608];
__device__ __align__(16) __nv_bfloat16 g_xlo[8388608];
__device__ __align__(16) __nv_bfloat16 g_yhi[8388608];
__device__ __align__(16) __nv_bfloat16 g_ylo[8388608];
__device__ __align__(16) __nv_bfloat16 g_whi[16777216];  // [q|k|v|o][2048][2048]
__device__ __align__(16) __nv_bfloat16 g_wlo[16777216];
__device__ __align__(16) __nv_bfloat16 g_qhi[8388608];
__device__ __align__(16) __nv_bfloat16 g_qlo[8388608];
__device__ __align__(16) __nv_bfloat16 g_khi[8388608];
__device__ __align__(16) __nv_bfloat16 g_klo[8388608];
__device__ __align__(16) __nv_bfloat16 g_vhi[8388608];
__device__ __align__(16) __nv_bfloat16 g_vlo[8388608];

// ===========================================================================
// fp32 -> bf16 hi/lo split kernels
// ===========================================================================
__device__ __forceinline__ void split4(float4 v, __nv_bfloat16* hi, __nv_bfloat16* lo) {
    __nv_bfloat16 h0 = __float2bfloat16(v.x), h1 = __float2bfloat16(v.y);
    __nv_bfloat16 h2 = __float2bfloat16(v.z), h3 = __float2bfloat16(v.w);
    __nv_bfloat16 l0 = __float2bfloat16(v.x - __bfloat162float(h0));
    __nv_bfloat16 l1 = __float2bfloat16(v.y - __bfloat162float(h1));
    __nv_bfloat16 l2 = __float2bfloat16(v.z - __bfloat162float(h2));
    __nv_bfloat16 l3 = __float2bfloat16(v.w - __bfloat162float(h3));
    __nv_bfloat162 p;
    p.x = h0; p.y = h1; *(__nv_bfloat162*)(hi)     = p;
    p.x = h2; p.y = h3; *(__nv_bfloat162*)(hi + 2) = p;
    p.x = l0; p.y = l1; *(__nv_bfloat162*)(lo)     = p;
    p.x = l2; p.y = l3; *(__nv_bfloat162*)(lo + 2) = p;
}

__global__ void split_xy_kernel(const float* __restrict__ x, int mode)
{
    int i = (blockIdx.x * 256 + threadIdx.x) * 4;
    const float* src = (mode == 0) ? x : (const float*)g_y;
    __nv_bfloat16* hi = (mode == 0) ? g_xhi : g_yhi;
    __nv_bfloat16* lo = (mode == 0) ? g_xlo : g_ylo;
    split4(*(const float4*)(src + i), hi + i, lo + i);
}

__global__ void split_w_kernel(const float* __restrict__ Wq, const float* __restrict__ Wk,
                               const float* __restrict__ Wv, const float* __restrict__ Wo)
{
    int j = blockIdx.y;
    const float* src = (j == 0) ? Wq : (j == 1) ? Wk : (j == 2) ? Wv : Wo;
    size_t base = (size_t)j * 4194304;
    int i = (blockIdx.x * 256 + threadIdx.x) * 4;
    split4(*(const float4*)(src + i), g_whi + base + i, g_wlo + base + i);
}

__global__ void split_qkv_kernel()
{
    int j = blockIdx.y;
    const float* src = (j == 0) ? g_q : (j == 1) ? g_k : g_v;
    __nv_bfloat16* hi = (j == 0) ? g_qhi : (j == 1) ? g_khi : g_vhi;
    __nv_bfloat16* lo = (j == 0) ? g_qlo : (j == 1) ? g_klo : g_vlo;
    int i = (blockIdx.x * 256 + threadIdx.x) * 4;
    split4(*(const float4*)(src + i), hi + i, lo + i);
}

// ===========================================================================
// LoRA left factor. mode 0: U = x @ dA^T (48 cols), mode 1: Uo = y @ doA^T
// ===========================================================================
__global__ void lora_u_kernel(const float* __restrict__ x,
                              const float* __restrict__ delta, int mode)
{
    int bt = blockIdx.x;
    int b  = bt >> 10;
    const float* src  = (mode == 0) ? x : (const float*)g_y;
    const float* xrow = src + (size_t)bt * CC;
    float* dst = (mode == 0) ? g_u : g_uo;
    int nOut   = (mode == 0) ? 48 : 16;

    int lane = threadIdx.x & 31, w = threadIdx.x >> 5;
    for (int j = w; j < nOut; j += 8) {
        int row = (mode == 0) ? ((j >> 4) * 32 + (j & 15)) : (96 + j);
        const float* arow = delta + ((size_t)b * 128 + row) * CC;
        float s = 0.f;
        for (int i = lane * 4; i < CC; i += 128) {
            float4 xv = *(const float4*)(xrow + i);
            float4 av = *(const float4*)(arow + i);
            s += xv.x * av.x + xv.y * av.y + xv.z * av.z + xv.w * av.w;
        }
        #pragma unroll
        for (int o = 16; o; o >>= 1) s += __shfl_xor_sync(0xffffffffu, s, o);
        if (lane == 0) dst[(size_t)bt * nOut + j] = s;
    }
}

// ===========================================================================
// bf16x3 GEMM on mma.sync + cp.async 3-stage pipeline.
// Tile 128(M) x 128(N), K-stage 32, 16 warps (4m x 4n), warp tile 32x32.
// 512 threads, <=128 regs -> 4 warps/SMSP. Smem rows padded to 80B.
// mode 0: QKV from g_xhi/g_xlo, head-layout out. mode 1: O from g_yhi/g_ylo.
// ===========================================================================
#define MMH_STAGE 40960
#define MMH_SMEM  (3 * MMH_STAGE)

__global__ __launch_bounds__(512, 1)
void mmh_kernel(const float* __restrict__ delta, int mode, float* __restrict__ outO)
{
    extern __shared__ __align__(16) char sm[];
    const int tid = threadIdx.x, lane = tid & 31, wid = tid >> 5;
    const int wm = wid >> 2, wn = wid & 3;     // 4m x 4n warps
    const int b = blockIdx.z, mt = blockIdx.y, nt = blockIdx.x;
    const int m0 = mt * 128, nbase = nt * 128;
    const int wrow0 = (mode == 0) ? nbase : (6144 + nbase);
    const size_t arow0 = (size_t)b * 1024 + m0;

    const __nv_bfloat16* Ahi = (mode == 0) ? g_xhi : g_yhi;
    const __nv_bfloat16* Alo = (mode == 0) ? g_xlo : g_ylo;
    const float* Uv = (mode == 0) ? g_u : g_uo;

    // loader: 512 threads, each owns 1 row x 16B seg in each of 4 sub-tiles
    const int lrow = tid >> 2, seg = tid & 3;
    const __nv_bfloat16* gAh = Ahi + (arow0 + lrow) * 2048 + seg * 8;
    const __nv_bfloat16* gAl = Alo + (arow0 + lrow) * 2048 + seg * 8;
    const __nv_bfloat16* gBh = g_whi + (size_t)(wrow0 + lrow) * 2048 + seg * 8;
    const __nv_bfloat16* gBl = g_wlo + (size_t)(wrow0 + lrow) * 2048 + seg * 8;
    const uint32_t so = (uint32_t)lrow * 80 + seg * 16;
    const uint32_t sb = smem_u32(sm);

    float acc[2][4][4];
    #pragma unroll
    for (int mi = 0; mi < 2; mi++)
        #pragma unroll
        for (int ni = 0; ni < 4; ni++)
            #pragma unroll
            for (int e = 0; e < 4; e++) acc[mi][ni][e] = 0.f;

    #define MMH_ISSUE(sbase, kt) do { \
        int kk = (kt) * 32; \
        CP_ASYNC16((sbase) + so,         gAh + kk); \
        CP_ASYNC16((sbase) + 10240 + so, gAl + kk); \
        CP_ASYNC16((sbase) + 20480 + so, gBh + kk); \
        CP_ASYNC16((sbase) + 30720 + so, gBl + kk); \
    } while (0)

    MMH_ISSUE(sb, 0);              CP_COMMIT();
    MMH_ISSUE(sb + MMH_STAGE, 1);  CP_COMMIT();

    const uint32_t aRowBase = (uint32_t)(wm * 32 + (lane & 15)) * 80 + (lane >> 4) * 16;
    const uint32_t bRowBase = (uint32_t)(wn * 32 + (lane & 15)) * 80 + (lane >> 4) * 16;

    int buf = 0, nxt = 2;
    for (int kt = 0; kt < 64; kt++) {
        CP_WAIT1();
        __syncthreads();
        if (kt < 62) MMH_ISSUE(sb + nxt * MMH_STAGE, kt + 2);
        CP_COMMIT();

        uint32_t sA = sb + buf * MMH_STAGE;
        uint32_t sB = sA + 20480;
        #pragma unroll
        for (int ks = 0; ks < 2; ks++) {
            uint32_t ah[2][4], al[2][4], bh[4][2], bl[4][2];
            #pragma unroll
            for (int mi = 0; mi < 2; mi++) {
                uint32_t ad = sA + aRowBase + mi * (16 * 80) + ks * 32;
                LDSM_X4(ah[mi], ad);
                LDSM_X4(al[mi], ad + 10240);
            }
            #pragma unroll
            for (int g = 0; g < 2; g++) {
                uint32_t bd = sB + bRowBase + g * (16 * 80) + ks * 32;
                uint32_t t[4], tl[4];
                LDSM_X4(t, bd);
                LDSM_X4(tl, bd + 10240);
                bh[g * 2][0] = t[0];  bh[g * 2][1] = t[2];
                bh[g * 2 + 1][0] = t[1]; bh[g * 2 + 1][1] = t[3];
                bl[g * 2][0] = tl[0]; bl[g * 2][1] = tl[2];
                bl[g * 2 + 1][0] = tl[1]; bl[g * 2 + 1][1] = tl[3];
            }
            #pragma unroll
            for (int mi = 0; mi < 2; mi++)
                #pragma unroll
                for (int ni = 0; ni < 4; ni++) {
                    MMA_BF16(acc[mi][ni], ah[mi], bh[ni]);
                    MMA_BF16(acc[mi][ni], al[mi], bh[ni]);
                    MMA_BF16(acc[mi][ni], ah[mi], bl[ni]);
                }
        }
        buf = (buf == 2) ? 0 : buf + 1;
        nxt = (nxt == 2) ? 0 : nxt + 1;
    }
    CP_WAIT0();
    __syncthreads();

    // ---- LoRA epilogue + writeback ----
    float* sU  = (float*)sm;               // [128][17]
    float* sDb = (float*)(sm + 12288);     // [16][136]
    const int seg2    = (mode == 0) ? (nbase >> 11) : 3;
    const int ncol0   = (mode == 0) ? (nbase & 2047) : nbase;
    const int dbrow   = (mode == 0) ? (seg2 * 32 + 16) : 112;
    const int ustride = (mode == 0) ? 48 : 16;
    const int uoff    = (mode == 0) ? seg2 * 16 : 0;

    if (tid < 128) {
        const float* up = Uv + ((size_t)b * 1024 + m0 + tid) * ustride + uoff;
        #pragma unroll
        for (int i = 0; i < 4; i++) {
            float4 v = *(const float4*)(up + i * 4);
            sU[tid * 17 + i * 4 + 0] = v.x;
            sU[tid * 17 + i * 4 + 1] = v.y;
            sU[tid * 17 + i * 4 + 2] = v.z;
            sU[tid * 17 + i * 4 + 3] = v.w;
        }
    }
    {
        int r = tid >> 5, c4 = (tid & 31) * 4;   // 512 threads = 16 rows x 32 quads
        float4 v = *(const float4*)(delta + ((size_t)b * 128 + dbrow + r) * 2048 + ncol0 + c4);
        *(float4*)(sDb + r * 136 + c4) = v;
    }
    __syncthreads();

    const int trow = lane >> 2;
    const int tcol = (lane & 3) * 2;
    float* qkvbase = (seg2 == 0) ? g_q : (seg2 == 1) ? g_k : g_v;

    #pragma unroll
    for (int mi = 0; mi < 2; mi++) {
        int lr0 = wm * 32 + mi * 16 + trow;
        int lr1 = lr0 + 8;
        #pragma unroll
        for (int r = 0; r < 16; r++) {
            float u0 = sU[lr0 * 17 + r];
            float u1 = sU[lr1 * 17 + r];
            #pragma unroll
            for (int ni = 0; ni < 4; ni++) {
                int c = wn * 32 + ni * 8 + tcol;
                float d0 = sDb[r * 136 + c];
                float d1 = sDb[r * 136 + c + 1];
                acc[mi][ni][0] += u0 * d0;
                acc[mi][ni][1] += u0 * d1;
                acc[mi][ni][2] += u1 * d0;
                acc[mi][ni][3] += u1 * d1;
            }
        }
        #pragma unroll
        for (int ni = 0; ni < 4; ni++) {
            int c = wn * 32 + ni * 8 + tcol;
            if (mode == 0) {
                int h = ncol0 >> 7;
                float* dst = qkvbase + (((size_t)b * 16 + h) * 1024 + m0) * 128;
                *(float2*)(dst + (size_t)lr0 * 128 + c) = make_float2(acc[mi][ni][0], acc[mi][ni][1]);
                *(float2*)(dst + (size_t)lr1 * 128 + c) = make_float2(acc[mi][ni][2], acc[mi][ni][3]);
            } else {
                float* dst = outO + ((size_t)b * 1024 + m0) * 2048 + nbase;
                *(float2*)(dst + (size_t)lr0 * 2048 + c) = make_float2(acc[mi][ni][0], acc[mi][ni][1]);
                *(float2*)(dst + (size_t)lr1 * 2048 + c) = make_float2(acc[mi][ni][2], acc[mi][ni][3]);
            }
        }
    }
}

// ===========================================================================
// RoPE in place on g_q, g_k
// ===========================================================================
__global__ void rope_kernel()
{
    int idx = blockIdx.x * 256 + threadIdx.x;
    if (idx >= BB * HH * TT * 64) return;
    int j  = idx & 63;
    int t  = (idx >> 6) & 1023;
    int bh = idx >> 16;
    float inv = exp2f(-(float)j * (13.2877123795f / 64.0f));
    float ang = (float)t * inv;
    float c, s;
    sincosf(ang, &s, &c);
    size_t base = ((size_t)bh * TT + t) * DD + j;
    float q1 = g_q[base], q2 = g_q[base + 64];
    g_q[base]      = q1 * c - q2 * s;
    g_q[base + 64] = q2 * c + q1 * s;
    float k1 = g_k[base], k2 = g_k[base + 64];
    g_k[base]      = k1 * c - k2 * s;
    g_k[base + 64] = k2 * c + k1 * s;
}

// ===========================================================================
// HMMA flash attention (round-10 passing version, unchanged)
// ===========================================================================
#define AT_PITCH 272
#define AT_QH 0
#define AT_QL 34816
#define AT_KH 69632
#define AT_KL 104448
#define AT_VH 139264
#define AT_VL 174080
#define AT_SMEM 208896

__device__ __forceinline__ void split_pack(float x, float y, uint32_t& hi, uint32_t& lo)
{
    __nv_bfloat16 hx = __float2bfloat16(x), hy = __float2bfloat16(y);
    __nv_bfloat16 lx = __float2bfloat16(x - __bfloat162float(hx));
    __nv_bfloat16 ly = __float2bfloat16(y - __bfloat162float(hy));
    __nv_bfloat162 h; h.x = hx; h.y = hy;
    __nv_bfloat162 l; l.x = lx; l.y = ly;
    hi = *(uint32_t*)&h;
    lo = *(uint32_t*)&l;
}

__global__ __launch_bounds__(256, 1) void attn_h_kernel()
{
    extern __shared__ __align__(16) char sm[];
    const int tid = threadIdx.x, lane = tid & 31, wid = tid >> 5;
    const int qt = blockIdx.x, bh = blockIdx.y;
    const int q0 = qt * 128;
    const size_t tbase = (size_t)bh * 1024;
    const uint32_t sb = smem_u32(sm);

    #pragma unroll
    for (int i = 0; i < 8; i++) {
        int s = tid + i * 256;
        int row = s >> 4, c = s & 15;
        uint32_t off = (uint32_t)row * AT_PITCH + c * 16;
        size_t g = (tbase + q0 + row) * 128 + c * 8;
        *(uint4*)(sm + AT_QH + off) = *(const uint4*)(g_qhi + g);
        *(uint4*)(sm + AT_QL + off) = *(const uint4*)(g_qlo + g);
    }

    const int gq = lane >> 2, t4 = lane & 3;
    const uint32_t ldRow = (uint32_t)(lane & 15) * AT_PITCH + (lane >> 4) * 16;
    const uint32_t qBase = sb + AT_QH + (uint32_t)(wid * 16) * AT_PITCH + ldRow;

    float o[16][4];
    #pragma unroll
    for (int n = 0; n < 16; n++)
        #pragma unroll
        for (int e = 0; e < 4; e++) o[n][e] = 0.f;
    float mA = -3.0e38f, mB = -3.0e38f, lA = 0.f, lB = 0.f;
    const float scale = 0.08838834764831845f;

    for (int kt = 0; kt < 8; kt++) {
        #pragma unroll
        for (int i = 0; i < 8; i++) {
            int s = tid + i * 256;
            int row = s >> 4, c = s & 15;
            uint32_t off = (uint32_t)row * AT_PITCH + c * 16;
            size_t g = (tbase + kt * 128 + row) * 128 + c * 8;
            *(uint4*)(sm + AT_KH + off) = *(const uint4*)(g_khi + g);
            *(uint4*)(sm + AT_KL + off) = *(const uint4*)(g_klo + g);
            *(uint4*)(sm + AT_VH + off) = *(const uint4*)(g_vhi + g);
            *(uint4*)(sm + AT_VL + off) = *(const uint4*)(g_vlo + g);
        }
        __syncthreads();

        float s[16][4];
        #pragma unroll
        for (int n = 0; n < 16; n++)
            #pragma unroll
            for (int e = 0; e < 4; e++) s[n][e] = 0.f;

        #pragma unroll
        for (int ks = 0; ks < 8; ks++) {
            uint32_t qh[4], ql[4];
            LDSM_X4(qh, qBase + ks * 32);
            LDSM_X4(ql, qBase + (AT_QL - AT_QH) + ks * 32);
            #pragma unroll
            for (int np = 0; np < 8; np++) {
                uint32_t th[4], tl[4];
                uint32_t ka = sb + AT_KH + ldRow + np * (16 * AT_PITCH) + ks * 32;
                LDSM_X4(th, ka);
                LDSM_X4(tl, ka + (AT_KL - AT_KH));
                uint32_t b0h[2] = {th[0], th[2]}, b1h[2] = {th[1], th[3]};
                uint32_t b0l[2] = {tl[0], tl[2]}, b1l[2] = {tl[1], tl[3]};
                MMA_BF16(s[2 * np],     qh, b0h);
                MMA_BF16(s[2 * np],     ql, b0h);
                MMA_BF16(s[2 * np],     qh, b0l);
                MMA_BF16(s[2 * np + 1], qh, b1h);
                MMA_BF16(s[2 * np + 1], ql, b1h);
                MMA_BF16(s[2 * np + 1], qh, b1l);
            }
        }

        float mxA = -3.0e38f, mxB = -3.0e38f;
        #pragma unroll
        for (int n = 0; n < 16; n++) {
            mxA = fmaxf(mxA, fmaxf(s[n][0], s[n][1]));
            mxB = fmaxf(mxB, fmaxf(s[n][2], s[n][3]));
        }
        mxA = fmaxf(mxA, __shfl_xor_sync(0xffffffffu, mxA, 1));
        mxA = fmaxf(mxA, __shfl_xor_sync(0xffffffffu, mxA, 2));
        mxB = fmaxf(mxB, __shfl_xor_sync(0xffffffffu, mxB, 1));
        mxB = fmaxf(mxB, __shfl_xor_sync(0xffffffffu, mxB, 2));
        float nmA = fmaxf(mA, mxA * scale);
        float nmB = fmaxf(mB, mxB * scale);
        float aA = __expf(mA - nmA), aB = __expf(mB - nmB);
        mA = nmA; mB = nmB;
        float sumA = 0.f, sumB = 0.f;
        #pragma unroll
        for (int n = 0; n < 16; n++) {
            s[n][0] = __expf(s[n][0] * scale - mA); sumA += s[n][0];
            s[n][1] = __expf(s[n][1] * scale - mA); sumA += s[n][1];
            s[n][2] = __expf(s[n][2] * scale - mB); sumB += s[n][2];
            s[n][3] = __expf(s[n][3] * scale - mB); sumB += s[n][3];
        }
        sumA += __shfl_xor_sync(0xffffffffu, sumA, 1);
        sumA += __shfl_xor_sync(0xffffffffu, sumA, 2);
        sumB += __shfl_xor_sync(0xffffffffu, sumB, 1);
        sumB += __shfl_xor_sync(0xffffffffu, sumB, 2);
        lA = lA * aA + sumA;
        lB = lB * aB + sumB;
        #pragma unroll
        for (int n = 0; n < 16; n++) {
            o[n][0] *= aA; o[n][1] *= aA;
            o[n][2] *= aB; o[n][3] *= aB;
        }

        #pragma unroll
        for (int kk = 0; kk < 8; kk++) {
            uint32_t ah[4], al[4];
            split_pack(s[2 * kk][0],     s[2 * kk][1],     ah[0], al[0]);
            split_pack(s[2 * kk][2],     s[2 * kk][3],     ah[1], al[1]);
            split_pack(s[2 * kk + 1][0], s[2 * kk + 1][1], ah[2], al[2]);
            split_pack(s[2 * kk + 1][2], s[2 * kk + 1][3], ah[3], al[3]);
            #pragma unroll
            for (int np = 0; np < 8; np++) {
                uint32_t tv[4], tw[4];
                uint32_t va = sb + AT_VH + ldRow + kk * (16 * AT_PITCH) + np * 32;
                LDSM_X4_T(tv, va);
                LDSM_X4_T(tw, va + (AT_VL - AT_VH));
                uint32_t b0h[2] = {tv[0], tv[1]}, b1h[2] = {tv[2], tv[3]};
                uint32_t b0l[2] = {tw[0], tw[1]}, b1l[2] = {tw[2], tw[3]};
                MMA_BF16(o[2 * np],     ah, b0h);
                MMA_BF16(o[2 * np],     al, b0h);
                MMA_BF16(o[2 * np],     ah, b0l);
                MMA_BF16(o[2 * np + 1], ah, b1h);
                MMA_BF16(o[2 * np + 1], al, b1h);
                MMA_BF16(o[2 * np + 1], ah, b1l);
            }
        }
        __syncthreads();
    }

    int b = bh >> 4, h = bh & 15;
    float iA = 1.f / lA, iB = 1.f / lB;
    int rA = q0 + wid * 16 + gq, rB = rA + 8;
    float* ybA = g_y + ((size_t)b * TT + rA) * CC + h * 128;
    float* ybB = g_y + ((size_t)b * TT + rB) * CC + h * 128;
    #pragma unroll
    for (int n = 0; n < 16; n++) {
        int d = n * 8 + t4 * 2;
        *(float2*)(ybA + d) = make_float2(o[n][0] * iA, o[n][1] * iA);
        *(float2*)(ybB + d) = make_float2(o[n][2] * iB, o[n][3] * iB);
    }
}

// ===========================================================================
extern "C" void kernel_launch(void* const* d_in, const int* in_sizes, int n_in,
                              void* d_out, int out_size)
{
    const float* x     = (const float*)d_in[0];
    const float* delta = (const float*)d_in[1];
    const float* Wq    = (const float*)d_in[2];
    const float* Wk    = (const float*)d_in[3];
    const float* Wv    = (const float*)d_in[4];
    const float* Wo    = (const float*)d_in[5];
    float* out = (float*)d_out;

    cudaFuncSetAttribute(mmh_kernel, cudaFuncAttributeMaxDynamicSharedMemorySize,
                         MMH_SMEM);
    cudaFuncSetAttribute(attn_h_kernel, cudaFuncAttributeMaxDynamicSharedMemorySize,
                         AT_SMEM);

    split_w_kernel<<<dim3(4096, 4), 256>>>(Wq, Wk, Wv, Wo);
    split_xy_kernel<<<8192, 256>>>(x, 0);
    lora_u_kernel<<<BB * TT, 256>>>(x, delta, 0);
    mmh_kernel<<<dim3(48, 8, BB), 512, MMH_SMEM>>>(delta, 0, nullptr);
    rope_kernel<<<(BB * HH * TT * 64) / 256, 256>>>();
    split_qkv_kernel<<<dim3(8192, 3), 256>>>();
    attn_h_kernel<<<dim3(8, BB * HH), 256, AT_SMEM>>>();
    lora_u_kernel<<<BB * TT, 256>>>(x, delta, 1);
    split_xy_kernel<<<8192, 256>>>(x, 1);
    mmh_kernel<<<dim3(16, 8, BB), 512, MMH_SMEM>>>(delta, 1, out);
}

// round 13
// speedup vs baseline: 3.3802x; 1.4321x over previous
#include <cuda_runtime.h>
#include <cuda_bf16.h>
#include <cuda_fp16.h>
#include <stdint.h>
#include <math.h>

#define BB 4
#define TT 1024
#define CC 2048
#define HH 16
#define DD 128

typedef unsigned long long u64;

__device__ __forceinline__ uint32_t smem_u32(const void* p) {
    uint32_t a;
    asm("{ .reg .u64 t; cvta.to.shared.u64 t, %1; cvt.u32.u64 %0, t; }" : "=r"(a) : "l"(p));
    return a;
}

// ===========================================================================
// HMMA path: ldmatrix + mma.sync + cp.async (sm_80 baseline ISA), fp16 kind
// ===========================================================================
#define LDSM_X4(r, addr) \
    asm volatile("ldmatrix.sync.aligned.m8n8.x4.shared.b16 {%0,%1,%2,%3}, [%4];" \
        : "=r"((r)[0]), "=r"((r)[1]), "=r"((r)[2]), "=r"((r)[3]) : "r"(addr))

#define LDSM_X4_T(r, addr) \
    asm volatile("ldmatrix.sync.aligned.m8n8.x4.trans.shared.b16 {%0,%1,%2,%3}, [%4];" \
        : "=r"((r)[0]), "=r"((r)[1]), "=r"((r)[2]), "=r"((r)[3]) : "r"(addr))

#define MMA_FP16(d, a, b) \
    asm volatile("mma.sync.aligned.m16n8k16.row.col.f32.f16.f16.f32 " \
        "{%0,%1,%2,%3}, {%4,%5,%6,%7}, {%8,%9}, {%0,%1,%2,%3};" \
        : "+f"((d)[0]), "+f"((d)[1]), "+f"((d)[2]), "+f"((d)[3]) \
        : "r"((a)[0]), "r"((a)[1]), "r"((a)[2]), "r"((a)[3]), \
          "r"((b)[0]), "r"((b)[1]))

#define CP_ASYNC16(saddr, gptr) \
    asm volatile("cp.async.cg.shared.global [%0], [%1], 16;" \
        :: "r"(saddr), "l"(gptr) : "memory")
#define CP_COMMIT() asm volatile("cp.async.commit_group;" ::: "memory")
#define CP_WAIT1()  asm volatile("cp.async.wait_group 1;" ::: "memory")
#define CP_WAIT0()  asm volatile("cp.async.wait_group 0;" ::: "memory")

// ===========================================================================
// Scratch (device globals — no allocation allowed)
// ===========================================================================
__device__ float g_q[8388608];   // (B,H,T,D)
__device__ float g_k[8388608];
__device__ float g_v[8388608];
__device__ float g_y[8388608];   // (B,T,C)
__device__ float g_u[196608];    // (B,T,48)
__device__ float g_uo[65536];    // (B,T,16)
__device__ __align__(16) __half g_xhi[8388608];
__device__ __align__(16) __half g_xlo[8388608];
__device__ __align__(16) __half g_yhi[8388608];
__device__ __align__(16) __half g_ylo[8388608];
__device__ __align__(16) __half g_whi[16777216];  // [q|k|v|o][2048][2048]
__device__ __align__(16) __half g_qhi[8388608];
__device__ __align__(16) __half g_qlo[8388608];
__device__ __align__(16) __half g_khi[8388608];
__device__ __align__(16) __half g_vhi[8388608];

// ===========================================================================
// fp32 -> fp16 split kernels
// ===========================================================================
__device__ __forceinline__ void split4h(float4 v, __half* hi, __half* lo) {
    __half h0 = __float2half_rn(v.x), h1 = __float2half_rn(v.y);
    __half h2 = __float2half_rn(v.z), h3 = __float2half_rn(v.w);
    __half l0 = __float2half_rn(v.x - __half2float(h0));
    __half l1 = __float2half_rn(v.y - __half2float(h1));
    __half l2 = __float2half_rn(v.z - __half2float(h2));
    __half l3 = __float2half_rn(v.w - __half2float(h3));
    __half2 p;
    p.x = h0; p.y = h1; *(__half2*)(hi)     = p;
    p.x = h2; p.y = h3; *(__half2*)(hi + 2) = p;
    p.x = l0; p.y = l1; *(__half2*)(lo)     = p;
    p.x = l2; p.y = l3; *(__half2*)(lo + 2) = p;
}
__device__ __forceinline__ void cvt4h(float4 v, __half* hi) {
    __half2 p;
    p.x = __float2half_rn(v.x); p.y = __float2half_rn(v.y);
    *(__half2*)(hi) = p;
    p.x = __float2half_rn(v.z); p.y = __float2half_rn(v.w);
    *(__half2*)(hi + 2) = p;
}

// mode 0: split x -> g_xhi/g_xlo.  mode 1: split g_y -> g_yhi/g_ylo.
__global__ void split_xy_kernel(const float* __restrict__ x, int mode)
{
    int i = (blockIdx.x * 256 + threadIdx.x) * 4;
    const float* src = (mode == 0) ? x : (const float*)g_y;
    __half* hi = (mode == 0) ? g_xhi : g_yhi;
    __half* lo = (mode == 0) ? g_xlo : g_ylo;
    split4h(*(const float4*)(src + i), hi + i, lo + i);
}

// W: hi only (the A-side carries the split)
__global__ void split_w_kernel(const float* __restrict__ Wq, const float* __restrict__ Wk,
                               const float* __restrict__ Wv, const float* __restrict__ Wo)
{
    int j = blockIdx.y;
    const float* src = (j == 0) ? Wq : (j == 1) ? Wk : (j == 2) ? Wv : Wo;
    size_t base = (size_t)j * 4194304;
    int i = (blockIdx.x * 256 + threadIdx.x) * 4;
    cvt4h(*(const float4*)(src + i), g_whi + base + i);
}

// q -> hi+lo; k,v -> hi only
__global__ void split_qkv_kernel()
{
    int j = blockIdx.y;
    int i = (blockIdx.x * 256 + threadIdx.x) * 4;
    if (j == 0) {
        split4h(*(const float4*)(g_q + i), g_qhi + i, g_qlo + i);
    } else if (j == 1) {
        cvt4h(*(const float4*)(g_k + i), g_khi + i);
    } else {
        cvt4h(*(const float4*)(g_v + i), g_vhi + i);
    }
}

// ===========================================================================
// LoRA left factor. mode 0: U = x @ dA^T (48 cols), mode 1: Uo = y @ doA^T
// ===========================================================================
__global__ void lora_u_kernel(const float* __restrict__ x,
                              const float* __restrict__ delta, int mode)
{
    int bt = blockIdx.x;
    int b  = bt >> 10;
    const float* src  = (mode == 0) ? x : (const float*)g_y;
    const float* xrow = src + (size_t)bt * CC;
    float* dst = (mode == 0) ? g_u : g_uo;
    int nOut   = (mode == 0) ? 48 : 16;

    int lane = threadIdx.x & 31, w = threadIdx.x >> 5;
    for (int j = w; j < nOut; j += 8) {
        int row = (mode == 0) ? ((j >> 4) * 32 + (j & 15)) : (96 + j);
        const float* arow = delta + ((size_t)b * 128 + row) * CC;
        float s = 0.f;
        for (int i = lane * 4; i < CC; i += 128) {
            float4 xv = *(const float4*)(xrow + i);
            float4 av = *(const float4*)(arow + i);
            s += xv.x * av.x + xv.y * av.y + xv.z * av.z + xv.w * av.w;
        }
        #pragma unroll
        for (int o = 16; o; o >>= 1) s += __shfl_xor_sync(0xffffffffu, s, o);
        if (lane == 0) dst[(size_t)bt * nOut + j] = s;
    }
}

// ===========================================================================
// fp16x2 GEMM on mma.sync + cp.async 3-stage pipeline.
// out = Ah*Bh + Al*Bh (B residual dropped; rel err ~1.4e-4).
// Tile 128x128, K-stage 32, 16 warps (4m x 4n), warp tile 32x32, 512 thr.
// ===========================================================================
#define MMH_STAGE 30720
#define MMH_SMEM  (3 * MMH_STAGE)

__global__ __launch_bounds__(512, 1)
void mmh_kernel(const float* __restrict__ delta, int mode, float* __restrict__ outO)
{
    extern __shared__ __align__(16) char sm[];
    const int tid = threadIdx.x, lane = tid & 31, wid = tid >> 5;
    const int wm = wid >> 2, wn = wid & 3;
    const int b = blockIdx.z, mt = blockIdx.y, nt = blockIdx.x;
    const int m0 = mt * 128, nbase = nt * 128;
    const int wrow0 = (mode == 0) ? nbase : (6144 + nbase);
    const size_t arow0 = (size_t)b * 1024 + m0;

    const __half* Ahi = (mode == 0) ? g_xhi : g_yhi;
    const __half* Alo = (mode == 0) ? g_xlo : g_ylo;
    const float* Uv = (mode == 0) ? g_u : g_uo;

    const int lrow = tid >> 2, seg = tid & 3;
    const __half* gAh = Ahi + (arow0 + lrow) * 2048 + seg * 8;
    const __half* gAl = Alo + (arow0 + lrow) * 2048 + seg * 8;
    const __half* gBh = g_whi + (size_t)(wrow0 + lrow) * 2048 + seg * 8;
    const uint32_t so = (uint32_t)lrow * 80 + seg * 16;
    const uint32_t sb = smem_u32(sm);

    float acc[2][4][4];
    #pragma unroll
    for (int mi = 0; mi < 2; mi++)
        #pragma unroll
        for (int ni = 0; ni < 4; ni++)
            #pragma unroll
            for (int e = 0; e < 4; e++) acc[mi][ni][e] = 0.f;

    #define MMH_ISSUE(sbase, kt) do { \
        int kk = (kt) * 32; \
        CP_ASYNC16((sbase) + so,         gAh + kk); \
        CP_ASYNC16((sbase) + 10240 + so, gAl + kk); \
        CP_ASYNC16((sbase) + 20480 + so, gBh + kk); \
    } while (0)

    MMH_ISSUE(sb, 0);              CP_COMMIT();
    MMH_ISSUE(sb + MMH_STAGE, 1);  CP_COMMIT();

    const uint32_t aRowBase = (uint32_t)(wm * 32 + (lane & 15)) * 80 + (lane >> 4) * 16;
    const uint32_t bRowBase = (uint32_t)(wn * 32 + (lane & 15)) * 80 + (lane >> 4) * 16;

    int buf = 0, nxt = 2;
    for (int kt = 0; kt < 64; kt++) {
        CP_WAIT1();
        __syncthreads();
        if (kt < 62) MMH_ISSUE(sb + nxt * MMH_STAGE, kt + 2);
        CP_COMMIT();

        uint32_t sA = sb + buf * MMH_STAGE;
        uint32_t sB = sA + 20480;
        #pragma unroll
        for (int ks = 0; ks < 2; ks++) {
            uint32_t ah[2][4], al[2][4], bh[4][2];
            #pragma unroll
            for (int mi = 0; mi < 2; mi++) {
                uint32_t ad = sA + aRowBase + mi * (16 * 80) + ks * 32;
                LDSM_X4(ah[mi], ad);
                LDSM_X4(al[mi], ad + 10240);
            }
            #pragma unroll
            for (int g = 0; g < 2; g++) {
                uint32_t bd = sB + bRowBase + g * (16 * 80) + ks * 32;
                uint32_t t[4];
                LDSM_X4(t, bd);
                bh[g * 2][0] = t[0];  bh[g * 2][1] = t[2];
                bh[g * 2 + 1][0] = t[1]; bh[g * 2 + 1][1] = t[3];
            }
            #pragma unroll
            for (int mi = 0; mi < 2; mi++)
                #pragma unroll
                for (int ni = 0; ni < 4; ni++) {
                    MMA_FP16(acc[mi][ni], ah[mi], bh[ni]);
                    MMA_FP16(acc[mi][ni], al[mi], bh[ni]);
                }
        }
        buf = (buf == 2) ? 0 : buf + 1;
        nxt = (nxt == 2) ? 0 : nxt + 1;
    }
    CP_WAIT0();
    __syncthreads();

    // ---- LoRA epilogue + writeback ----
    float* sU  = (float*)sm;               // [128][17]
    float* sDb = (float*)(sm + 12288);     // [16][136]
    const int seg2    = (mode == 0) ? (nbase >> 11) : 3;
    const int ncol0   = (mode == 0) ? (nbase & 2047) : nbase;
    const int dbrow   = (mode == 0) ? (seg2 * 32 + 16) : 112;
    const int ustride = (mode == 0) ? 48 : 16;
    const int uoff    = (mode == 0) ? seg2 * 16 : 0;

    if (tid < 128) {
        const float* up = Uv + ((size_t)b * 1024 + m0 + tid) * ustride + uoff;
        #pragma unroll
        for (int i = 0; i < 4; i++) {
            float4 v = *(const float4*)(up + i * 4);
            sU[tid * 17 + i * 4 + 0] = v.x;
            sU[tid * 17 + i * 4 + 1] = v.y;
            sU[tid * 17 + i * 4 + 2] = v.z;
            sU[tid * 17 + i * 4 + 3] = v.w;
        }
    }
    {
        int r = tid >> 5, c4 = (tid & 31) * 4;
        float4 v = *(const float4*)(delta + ((size_t)b * 128 + dbrow + r) * 2048 + ncol0 + c4);
        *(float4*)(sDb + r * 136 + c4) = v;
    }
    __syncthreads();

    const int trow = lane >> 2;
    const int tcol = (lane & 3) * 2;
    float* qkvbase = (seg2 == 0) ? g_q : (seg2 == 1) ? g_k : g_v;

    #pragma unroll
    for (int mi = 0; mi < 2; mi++) {
        int lr0 = wm * 32 + mi * 16 + trow;
        int lr1 = lr0 + 8;
        #pragma unroll
        for (int r = 0; r < 16; r++) {
            float u0 = sU[lr0 * 17 + r];
            float u1 = sU[lr1 * 17 + r];
            #pragma unroll
            for (int ni = 0; ni < 4; ni++) {
                int c = wn * 32 + ni * 8 + tcol;
                float d0 = sDb[r * 136 + c];
                float d1 = sDb[r * 136 + c + 1];
                acc[mi][ni][0] += u0 * d0;
                acc[mi][ni][1] += u0 * d1;
                acc[mi][ni][2] += u1 * d0;
                acc[mi][ni][3] += u1 * d1;
            }
        }
        #pragma unroll
        for (int ni = 0; ni < 4; ni++) {
            int c = wn * 32 + ni * 8 + tcol;
            if (mode == 0) {
                int h = ncol0 >> 7;
                float* dst = qkvbase + (((size_t)b * 16 + h) * 1024 + m0) * 128;
                *(float2*)(dst + (size_t)lr0 * 128 + c) = make_float2(acc[mi][ni][0], acc[mi][ni][1]);
                *(float2*)(dst + (size_t)lr1 * 128 + c) = make_float2(acc[mi][ni][2], acc[mi][ni][3]);
            } else {
                float* dst = outO + ((size_t)b * 1024 + m0) * 2048 + nbase;
                *(float2*)(dst + (size_t)lr0 * 2048 + c) = make_float2(acc[mi][ni][0], acc[mi][ni][1]);
                *(float2*)(dst + (size_t)lr1 * 2048 + c) = make_float2(acc[mi][ni][2], acc[mi][ni][3]);
            }
        }
    }
}

// ===========================================================================
// RoPE in place on g_q, g_k
// ===========================================================================
__global__ void rope_kernel()
{
    int idx = blockIdx.x * 256 + threadIdx.x;
    if (idx >= BB * HH * TT * 64) return;
    int j  = idx & 63;
    int t  = (idx >> 6) & 1023;
    int bh = idx >> 16;
    float inv = exp2f(-(float)j * (13.2877123795f / 64.0f));
    float ang = (float)t * inv;
    float c, s;
    sincosf(ang, &s, &c);
    size_t base = ((size_t)bh * TT + t) * DD + j;
    float q1 = g_q[base], q2 = g_q[base + 64];
    g_q[base]      = q1 * c - q2 * s;
    g_q[base + 64] = q2 * c + q1 * s;
    float k1 = g_k[base], k2 = g_k[base + 64];
    g_k[base]      = k1 * c - k2 * s;
    g_k[base + 64] = k2 * c + k1 * s;
}

// ===========================================================================
// HMMA flash attention, fp16x2: QK^T = qh*kh + ql*kh, PV = ph*vh + pl*vh.
// Grid (T/128, B*H), 256 thr. smem: Qhi, Qlo, Khi, Vhi at 272B pitch.
// ===========================================================================
#define AT_PITCH 272
#define AT_QH 0
#define AT_QL 34816
#define AT_KH 69632
#define AT_VH 104448
#define AT_SMEM 139264

__device__ __forceinline__ void split_pack_h(float x, float y, uint32_t& hi, uint32_t& lo)
{
    __half hx = __float2half_rn(x), hy = __float2half_rn(y);
    __half lx = __float2half_rn(x - __half2float(hx));
    __half ly = __float2half_rn(y - __half2float(hy));
    __half2 h; h.x = hx; h.y = hy;
    __half2 l; l.x = lx; l.y = ly;
    hi = *(uint32_t*)&h;
    lo = *(uint32_t*)&l;
}

__global__ __launch_bounds__(256, 1) void attn_h_kernel()
{
    extern __shared__ __align__(16) char sm[];
    const int tid = threadIdx.x, lane = tid & 31, wid = tid >> 5;
    const int qt = blockIdx.x, bh = blockIdx.y;
    const int q0 = qt * 128;
    const size_t tbase = (size_t)bh * 1024;
    const uint32_t sb = smem_u32(sm);

    #pragma unroll
    for (int i = 0; i < 8; i++) {
        int s = tid + i * 256;
        int row = s >> 4, c = s & 15;
        uint32_t off = (uint32_t)row * AT_PITCH + c * 16;
        size_t g = (tbase + q0 + row) * 128 + c * 8;
        *(uint4*)(sm + AT_QH + off) = *(const uint4*)(g_qhi + g);
        *(uint4*)(sm + AT_QL + off) = *(const uint4*)(g_qlo + g);
    }

    const int gq = lane >> 2, t4 = lane & 3;
    const uint32_t ldRow = (uint32_t)(lane & 15) * AT_PITCH + (lane >> 4) * 16;
    const uint32_t qBase = sb + AT_QH + (uint32_t)(wid * 16) * AT_PITCH + ldRow;

    float o[16][4];
    #pragma unroll
    for (int n = 0; n < 16; n++)
        #pragma unroll
        for (int e = 0; e < 4; e++) o[n][e] = 0.f;
    float mA = -3.0e38f, mB = -3.0e38f, lA = 0.f, lB = 0.f;
    const float scale = 0.08838834764831845f;

    for (int kt = 0; kt < 8; kt++) {
        #pragma unroll
        for (int i = 0; i < 8; i++) {
            int s = tid + i * 256;
            int row = s >> 4, c = s & 15;
            uint32_t off = (uint32_t)row * AT_PITCH + c * 16;
            size_t g = (tbase + kt * 128 + row) * 128 + c * 8;
            *(uint4*)(sm + AT_KH + off) = *(const uint4*)(g_khi + g);
            *(uint4*)(sm + AT_VH + off) = *(const uint4*)(g_vhi + g);
        }
        __syncthreads();

        float s[16][4];
        #pragma unroll
        for (int n = 0; n < 16; n++)
            #pragma unroll
            for (int e = 0; e < 4; e++) s[n][e] = 0.f;

        #pragma unroll
        for (int ks = 0; ks < 8; ks++) {
            uint32_t qh[4], ql[4];
            LDSM_X4(qh, qBase + ks * 32);
            LDSM_X4(ql, qBase + (AT_QL - AT_QH) + ks * 32);
            #pragma unroll
            for (int np = 0; np < 8; np++) {
                uint32_t th[4];
                uint32_t ka = sb + AT_KH + ldRow + np * (16 * AT_PITCH) + ks * 32;
                LDSM_X4(th, ka);
                uint32_t b0h[2] = {th[0], th[2]}, b1h[2] = {th[1], th[3]};
                MMA_FP16(s[2 * np],     qh, b0h);
                MMA_FP16(s[2 * np],     ql, b0h);
                MMA_FP16(s[2 * np + 1], qh, b1h);
                MMA_FP16(s[2 * np + 1], ql, b1h);
            }
        }

        float mxA = -3.0e38f, mxB = -3.0e38f;
        #pragma unroll
        for (int n = 0; n < 16; n++) {
            mxA = fmaxf(mxA, fmaxf(s[n][0], s[n][1]));
            mxB = fmaxf(mxB, fmaxf(s[n][2], s[n][3]));
        }
        mxA = fmaxf(mxA, __shfl_xor_sync(0xffffffffu, mxA, 1));
        mxA = fmaxf(mxA, __shfl_xor_sync(0xffffffffu, mxA, 2));
        mxB = fmaxf(mxB, __shfl_xor_sync(0xffffffffu, mxB, 1));
        mxB = fmaxf(mxB, __shfl_xor_sync(0xffffffffu, mxB, 2));
        float nmA = fmaxf(mA, mxA * scale);
        float nmB = fmaxf(mB, mxB * scale);
        float aA = __expf(mA - nmA), aB = __expf(mB - nmB);
        mA = nmA; mB = nmB;
        float sumA = 0.f, sumB = 0.f;
        #pragma unroll
        for (int n = 0; n < 16; n++) {
            s[n][0] = __expf(s[n][0] * scale - mA); sumA += s[n][0];
            s[n][1] = __expf(s[n][1] * scale - mA); sumA += s[n][1];
            s[n][2] = __expf(s[n][2] * scale - mB); sumB += s[n][2];
            s[n][3] = __expf(s[n][3] * scale - mB); sumB += s[n][3];
        }
        sumA += __shfl_xor_sync(0xffffffffu, sumA, 1);
        sumA += __shfl_xor_sync(0xffffffffu, sumA, 2);
        sumB += __shfl_xor_sync(0xffffffffu, sumB, 1);
        sumB += __shfl_xor_sync(0xffffffffu, sumB, 2);
        lA = lA * aA + sumA;
        lB = lB * aB + sumB;
        #pragma unroll
        for (int n = 0; n < 16; n++) {
            o[n][0] *= aA; o[n][1] *= aA;
            o[n][2] *= aB; o[n][3] *= aB;
        }

        #pragma unroll
        for (int kk = 0; kk < 8; kk++) {
            uint32_t ph[4], pl[4];
            split_pack_h(s[2 * kk][0],     s[2 * kk][1],     ph[0], pl[0]);
            split_pack_h(s[2 * kk][2],     s[2 * kk][3],     ph[1], pl[1]);
            split_pack_h(s[2 * kk + 1][0], s[2 * kk + 1][1], ph[2], pl[2]);
            split_pack_h(s[2 * kk + 1][2], s[2 * kk + 1][3], ph[3], pl[3]);
            #pragma unroll
            for (int np = 0; np < 8; np++) {
                uint32_t tv[4];
                uint32_t va = sb + AT_VH + ldRow + kk * (16 * AT_PITCH) + np * 32;
                LDSM_X4_T(tv, va);
                uint32_t b0[2] = {tv[0], tv[1]}, b1[2] = {tv[2], tv[3]};
                MMA_FP16(o[2 * np],     ph, b0);
                MMA_FP16(o[2 * np],     pl, b0);
                MMA_FP16(o[2 * np + 1], ph, b1);
                MMA_FP16(o[2 * np + 1], pl, b1);
            }
        }
        __syncthreads();
    }

    int b = bh >> 4, h = bh & 15;
    float iA = 1.f / lA, iB = 1.f / lB;
    int rA = q0 + wid * 16 + gq, rB = rA + 8;
    float* ybA = g_y + ((size_t)b * TT + rA) * CC + h * 128;
    float* ybB = g_y + ((size_t)b * TT + rB) * CC + h * 128;
    #pragma unroll
    for (int n = 0; n < 16; n++) {
        int d = n * 8 + t4 * 2;
        *(float2*)(ybA + d) = make_float2(o[n][0] * iA, o[n][1] * iA);
        *(float2*)(ybB + d) = make_float2(o[n][2] * iB, o[n][3] * iB);
    }
}

// ===========================================================================
extern "C" void kernel_launch(void* const* d_in, const int* in_sizes, int n_in,
                              void* d_out, int out_size)
{
    const float* x     = (const float*)d_in[0];
    const float* delta = (const float*)d_in[1];
    const float* Wq    = (const float*)d_in[2];
    const float* Wk    = (const float*)d_in[3];
    const float* Wv    = (const float*)d_in[4];
    const float* Wo    = (const float*)d_in[5];
    float* out = (float*)d_out;

    cudaFuncSetAttribute(mmh_kernel, cudaFuncAttributeMaxDynamicSharedMemorySize,
                         MMH_SMEM);
    cudaFuncSetAttribute(attn_h_kernel, cudaFuncAttributeMaxDynamicSharedMemorySize,
                         AT_SMEM);

    split_w_kernel<<<dim3(4096, 4), 256>>>(Wq, Wk, Wv, Wo);
    split_xy_kernel<<<8192, 256>>>(x, 0);
    lora_u_kernel<<<BB * TT, 256>>>(x, delta, 0);
    mmh_kernel<<<dim3(48, 8, BB), 512, MMH_SMEM>>>(delta, 0, nullptr);
    rope_kernel<<<(BB * HH * TT * 64) / 256, 256>>>();
    split_qkv_kernel<<<dim3(8192, 3), 256>>>();
    attn_h_kernel<<<dim3(8, BB * HH), 256, AT_SMEM>>>();
    lora_u_kernel<<<BB * TT, 256>>>(x, delta, 1);
    split_xy_kernel<<<8192, 256>>>(x, 1);
    mmh_kernel<<<dim3(16, 8, BB), 512, MMH_SMEM>>>(delta, 1, out);
}